// round 13
// baseline (speedup 1.0000x reference)
#include <cuda_runtime.h>
#include <cuda_fp16.h>
#include <stdint.h>

#define NHEADS 16
#define BATCH  2
#define SEQ    2048
#define DMODEL 1024
#define HID    64
#define MROWS  4096
#define KPAIRS 512          // DMODEL/2
#define NORM   0.125f
#define NP     (MROWS*KPAIRS)
#define WN     (DMODEL*KPAIRS)
#define NSM2   296          // 2 CTAs x 148 SMs: one full wave

// ---------------------------------------------------------------------------
// Global scratch. Inputs + Q + H are hi-only; K,V and weights are split.
// ---------------------------------------------------------------------------
__device__ uint32_t g_Xh[3u*NP];                  // inputs hi [which][m][kpair]
__device__ uint32_t g_Wh[4u*WN], g_Wl[4u*WN];     // weights hi/lo [which][n][kpair]
__device__ uint32_t g_Qh[NP];                     // [h][b][s][32 epairs] (hi only)
__device__ uint32_t g_Kh[NP], g_Kl[NP];
__device__ uint32_t g_Vh[NP], g_Vl[NP];
__device__ uint32_t g_Hh[NP];                     // attn out hi [b][s][512 pairs]

// ---------------------------------------------------------------------------
// helpers
// ---------------------------------------------------------------------------
__device__ __forceinline__ void split2(float x, float y, uint32_t& hi, uint32_t& lo) {
    __half hx = __float2half_rn(x), hy = __float2half_rn(y);
    __half2 H = __halves2half2(hx, hy);
    __half2 L = __floats2half2_rn(x - __half2float(hx), y - __half2float(hy));
    hi = *reinterpret_cast<uint32_t*>(&H);
    lo = *reinterpret_cast<uint32_t*>(&L);
}
__device__ __forceinline__ uint32_t pack2(float x, float y) {
    __half2 H = __floats2half2_rn(x, y);
    return *reinterpret_cast<uint32_t*>(&H);
}
__device__ __forceinline__ uint32_t smem_u32(const void* p) {
    return (uint32_t)__cvta_generic_to_shared(p);
}
__device__ __forceinline__ void ldsm_x4(uint32_t* r, uint32_t addr) {
    asm volatile("ldmatrix.sync.aligned.m8n8.x4.shared.b16 {%0,%1,%2,%3},[%4];"
        : "=r"(r[0]), "=r"(r[1]), "=r"(r[2]), "=r"(r[3]) : "r"(addr));
}
__device__ __forceinline__ void ldsm_x4t(uint32_t* r, uint32_t addr) {
    asm volatile("ldmatrix.sync.aligned.m8n8.x4.trans.shared.b16 {%0,%1,%2,%3},[%4];"
        : "=r"(r[0]), "=r"(r[1]), "=r"(r[2]), "=r"(r[3]) : "r"(addr));
}
// fp32-accumulate fp16 MMA
__device__ __forceinline__ void mma16(float4& d, const uint32_t* a,
                                      uint32_t b0, uint32_t b1) {
    asm volatile(
        "mma.sync.aligned.m16n8k16.row.col.f32.f16.f16.f32 "
        "{%0,%1,%2,%3},{%4,%5,%6,%7},{%8,%9},{%0,%1,%2,%3};"
        : "+f"(d.x), "+f"(d.y), "+f"(d.z), "+f"(d.w)
        : "r"(a[0]), "r"(a[1]), "r"(a[2]), "r"(a[3]), "r"(b0), "r"(b1));
}
// fp16-accumulate fp16 MMA — lo correction terms only
__device__ __forceinline__ void mma16h(uint2& d, const uint32_t* a,
                                       uint32_t b0, uint32_t b1) {
    asm volatile(
        "mma.sync.aligned.m16n8k16.row.col.f16.f16.f16.f16 "
        "{%0,%1},{%2,%3,%4,%5},{%6,%7},{%0,%1};"
        : "+r"(d.x), "+r"(d.y)
        : "r"(a[0]), "r"(a[1]), "r"(a[2]), "r"(a[3]), "r"(b0), "r"(b1));
}
__device__ __forceinline__ void cp16(uint32_t dst, const void* src) {
    asm volatile("cp.async.cg.shared.global [%0], [%1], 16;" :: "r"(dst), "l"(src));
}
#define CP_COMMIT() asm volatile("cp.async.commit_group;")
#define CP_WAIT(N)  asm volatile("cp.async.wait_group %0;" :: "n"(N))

// ---------------------------------------------------------------------------
// presplit kernels
// ---------------------------------------------------------------------------
__global__ void presplit_hi3(const float* __restrict__ s0,
                             const float* __restrict__ s1,
                             const float* __restrict__ s2) {
    int z = blockIdx.z;
    const float* src = (z == 0) ? s0 : (z == 1) ? s1 : s2;
    int i = blockIdx.x * 256 + threadIdx.x;
    float2 v = ((const float2*)src)[i];
    g_Xh[(size_t)z * NP + i] = pack2(v.x, v.y);
}
__global__ void presplit_wqkv3(const float* __restrict__ W0,
                               const float* __restrict__ W1,
                               const float* __restrict__ W2) {
    int z = blockIdx.z;
    const float* W = (z == 0) ? W0 : (z == 1) ? W1 : W2;
    float scale = (z == 0) ? NORM : 1.0f;
    int i = blockIdx.x * 256 + threadIdx.x;
    int n = i >> 9, p = i & 511;
    int h = n >> 6, e = n & 63;
    const float* s = W + (size_t)h * DMODEL * HID + (size_t)(2 * p) * HID + e;
    uint32_t hh, ll; split2(s[0] * scale, s[HID] * scale, hh, ll);
    g_Wh[(size_t)z * WN + i] = hh;
    g_Wl[(size_t)z * WN + i] = ll;
}
__global__ void presplit_wo(const float* __restrict__ W) {
    int i = blockIdx.x * 256 + threadIdx.x;
    int n = i >> 9, p = i & 511;
    uint32_t hh, ll;
    split2(W[(size_t)(2 * p) * DMODEL + n], W[(size_t)(2 * p + 1) * DMODEL + n], hh, ll);
    g_Wh[3u * WN + i] = hh;
    g_Wl[3u * WN + i] = ll;
}

// ---------------------------------------------------------------------------
// QKV projection GEMM — PERSISTENT: grid=296, each block loops over the 768
// (z, m-tile, n-tile) work items. Per-tile math identical to R12 (bitwise).
// hi term Ah·Bh fp32 acc; lo term Ah·Bl fp16 acc, merged after the K loop.
// BM=BN=128, BK=64, 8 warps (4m x 2n), cp.async double-buffered.
// ---------------------------------------------------------------------------
#define GEMM_SMEM (2 * 3 * 4608 * 4)   // 110592 B

__global__ __launch_bounds__(256, 2)
void gemm_qkv()
{
    extern __shared__ uint32_t sg[];   // [2][3][4608]

    const int tid  = threadIdx.x;
    const int lane = tid & 31;
    const int wid  = tid >> 5;
    const int g    = lane >> 2;
    const int qd   = lane & 3;
    const int wm   = wid >> 1;
    const int wn   = wid & 1;

    const uint32_t SB = smem_u32(sg);
    const int arow = lane & 15, acol = (lane >> 4) * 4;
    const uint32_t a_off0 = ((wm * 32 + arow) * 36 + acol) * 4;
    const uint32_t a_off1 = a_off0 + 16 * 36 * 4;
    const uint32_t b_off0 = ((wn * 64 + lane) * 36) * 4;
    const uint32_t b_off1 = b_off0 + 32 * 36 * 4;

    for (int it = blockIdx.x; it < 768; it += NSM2) {
        const int z  = it >> 8;            // 0..2
        const int r  = it & 255;
        const int m0 = (r >> 3) * 128;
        const int n0 = (r & 7) * 128;

        const uint32_t* Ahg = g_Xh + (size_t)z * NP;
        const uint32_t* Bhg = g_Wh + (size_t)z * WN;
        const uint32_t* Blg = g_Wl + (size_t)z * WN;

        float4 acc[2][8];
        uint2  accl[2][8];
        #pragma unroll
        for (int i = 0; i < 2; i++)
            #pragma unroll
            for (int j = 0; j < 8; j++) {
                acc[i][j]  = make_float4(0.f, 0.f, 0.f, 0.f);
                accl[i][j] = make_uint2(0u, 0u);
            }

        auto load_tile = [&](int kt, int bf) {
            const uint32_t base = SB + (uint32_t)bf * 13824 * 4;
            int kp0 = kt * 32;
            #pragma unroll
            for (int t = 0; t < 12; t++) {
                int f = tid + t * 256;            // 0..3071
                int arr = f >> 10, gg = f & 1023;
                int row = gg >> 3, ch = gg & 7;
                uint32_t dst = base + (uint32_t)(arr * 4608 + row * 36 + ch * 4) * 4;
                const uint32_t* src =
                    (arr == 0) ? Ahg + (size_t)(m0 + row) * KPAIRS + kp0 + ch * 4 :
                    (arr == 1) ? Bhg + (size_t)(n0 + row) * KPAIRS + kp0 + ch * 4 :
                                 Blg + (size_t)(n0 + row) * KPAIRS + kp0 + ch * 4;
                cp16(dst, src);
            }
        };

        load_tile(0, 0);
        CP_COMMIT();

        for (int kt = 0; kt < 16; kt++) {
            if (kt < 15) { load_tile(kt + 1, (kt + 1) & 1); CP_COMMIT(); CP_WAIT(1); }
            else         { CP_WAIT(0); }
            __syncthreads();

            const uint32_t base = SB + (uint32_t)(kt & 1) * 13824 * 4;
            const uint32_t AHB = base;
            const uint32_t BHB = base + 4608 * 4, BLB = base + 9216 * 4;

            #pragma unroll
            for (int s = 0; s < 4; s++) {
                uint32_t sc = s * 32;
                uint32_t ah0[4], ah1[4];
                ldsm_x4(ah0, AHB + a_off0 + sc);
                ldsm_x4(ah1, AHB + a_off1 + sc);
                #pragma unroll
                for (int hb = 0; hb < 2; hb++) {
                    uint32_t boff = (hb ? b_off1 : b_off0) + sc;
                    uint32_t bh0[4], bh1[4], bl0[4], bl1[4];
                    ldsm_x4(bh0, BHB + boff);
                    ldsm_x4(bh1, BHB + boff + 16);
                    ldsm_x4(bl0, BLB + boff);
                    ldsm_x4(bl1, BLB + boff + 16);
                    #pragma unroll
                    for (int j = 0; j < 4; j++) mma16(acc[0][hb*4+j], ah0, bh0[j], bh1[j]);
                    #pragma unroll
                    for (int j = 0; j < 4; j++) mma16(acc[1][hb*4+j], ah1, bh0[j], bh1[j]);
                    #pragma unroll
                    for (int j = 0; j < 4; j++) mma16h(accl[0][hb*4+j], ah0, bl0[j], bl1[j]);
                    #pragma unroll
                    for (int j = 0; j < 4; j++) mma16h(accl[1][hb*4+j], ah1, bl0[j], bl1[j]);
                }
            }
            __syncthreads();
        }

        // Merge lo (fp16) into hi (fp32); epilogue
        #pragma unroll
        for (int mf = 0; mf < 2; mf++) {
            int mA = m0 + wm * 32 + mf * 16 + g;
            int mB = mA + 8;
            #pragma unroll
            for (int nf = 0; nf < 8; nf++) {
                float2 l0 = __half22float2(*reinterpret_cast<__half2*>(&accl[mf][nf].x));
                float2 l1 = __half22float2(*reinterpret_cast<__half2*>(&accl[mf][nf].y));
                float4 c = acc[mf][nf];
                c.x += l0.x; c.y += l0.y; c.z += l1.x; c.w += l1.y;
                int head = (n0 >> 6) + wn;
                int pr   = nf * 4 + qd;
                int bA = mA >> 11, sA = mA & 2047;
                int bB = mB >> 11, sB = mB & 2047;
                size_t dA = (((size_t)head * BATCH + bA) * SEQ + sA) * 32 + pr;
                size_t dB = (((size_t)head * BATCH + bB) * SEQ + sB) * 32 + pr;
                if (z == 0) {
                    g_Qh[dA] = pack2(c.x, c.y);
                    g_Qh[dB] = pack2(c.z, c.w);
                } else {
                    uint32_t* Oh = (z == 1) ? g_Kh : g_Vh;
                    uint32_t* Ol = (z == 1) ? g_Kl : g_Vl;
                    uint32_t hh, ll;
                    split2(c.x, c.y, hh, ll);
                    Oh[dA] = hh; Ol[dA] = ll;
                    split2(c.z, c.w, hh, ll);
                    Oh[dB] = hh; Ol[dB] = ll;
                }
            }
        }
    }
}

// ---------------------------------------------------------------------------
// Output projection GEMM: hi term fp32 acc, lo term fp16 acc. BK=64.
// 256 blocks (< 1 wave) — not persistent.
// ---------------------------------------------------------------------------
__global__ __launch_bounds__(256, 2)
void gemm_out(float* __restrict__ Outf)
{
    extern __shared__ uint32_t sg[];   // [2][3][4608]

    const int tid  = threadIdx.x;
    const int lane = tid & 31;
    const int wid  = tid >> 5;
    const int g    = lane >> 2;
    const int qd   = lane & 3;
    const int wm   = wid >> 1;
    const int wn   = wid & 1;
    const int m0   = blockIdx.y * 128;
    const int n0   = blockIdx.x * 128;

    const uint32_t* Ahg = g_Hh;
    const uint32_t* Bhg = g_Wh + 3u * WN;
    const uint32_t* Blg = g_Wl + 3u * WN;

    const uint32_t SB = smem_u32(sg);
    const int arow = lane & 15, acol = (lane >> 4) * 4;
    const uint32_t a_off0 = ((wm * 32 + arow) * 36 + acol) * 4;
    const uint32_t a_off1 = a_off0 + 16 * 36 * 4;
    const uint32_t b_off0 = ((wn * 64 + lane) * 36) * 4;
    const uint32_t b_off1 = b_off0 + 32 * 36 * 4;

    float4 acc[2][8];
    uint2  accl[2][8];
    #pragma unroll
    for (int i = 0; i < 2; i++)
        #pragma unroll
        for (int j = 0; j < 8; j++) {
            acc[i][j]  = make_float4(0.f, 0.f, 0.f, 0.f);
            accl[i][j] = make_uint2(0u, 0u);
        }

    auto load_tile = [&](int kt, int bf) {
        const uint32_t base = SB + (uint32_t)bf * 13824 * 4;
        int kp0 = kt * 32;
        #pragma unroll
        for (int t = 0; t < 12; t++) {
            int f = tid + t * 256;
            int arr = f >> 10, gg = f & 1023;
            int row = gg >> 3, ch = gg & 7;
            uint32_t dst = base + (uint32_t)(arr * 4608 + row * 36 + ch * 4) * 4;
            const uint32_t* src =
                (arr == 0) ? Ahg + (size_t)(m0 + row) * KPAIRS + kp0 + ch * 4 :
                (arr == 1) ? Bhg + (size_t)(n0 + row) * KPAIRS + kp0 + ch * 4 :
                             Blg + (size_t)(n0 + row) * KPAIRS + kp0 + ch * 4;
            cp16(dst, src);
        }
    };

    load_tile(0, 0);
    CP_COMMIT();

    for (int kt = 0; kt < 16; kt++) {
        if (kt < 15) { load_tile(kt + 1, (kt + 1) & 1); CP_COMMIT(); CP_WAIT(1); }
        else         { CP_WAIT(0); }
        __syncthreads();

        const uint32_t base = SB + (uint32_t)(kt & 1) * 13824 * 4;
        const uint32_t AHB = base;
        const uint32_t BHB = base + 4608 * 4, BLB = base + 9216 * 4;

        #pragma unroll
        for (int s = 0; s < 4; s++) {
            uint32_t sc = s * 32;
            uint32_t ah0[4], ah1[4];
            ldsm_x4(ah0, AHB + a_off0 + sc);
            ldsm_x4(ah1, AHB + a_off1 + sc);
            #pragma unroll
            for (int hb = 0; hb < 2; hb++) {
                uint32_t boff = (hb ? b_off1 : b_off0) + sc;
                uint32_t bh0[4], bh1[4], bl0[4], bl1[4];
                ldsm_x4(bh0, BHB + boff);
                ldsm_x4(bh1, BHB + boff + 16);
                ldsm_x4(bl0, BLB + boff);
                ldsm_x4(bl1, BLB + boff + 16);
                #pragma unroll
                for (int j = 0; j < 4; j++) mma16(acc[0][hb*4+j], ah0, bh0[j], bh1[j]);
                #pragma unroll
                for (int j = 0; j < 4; j++) mma16(acc[1][hb*4+j], ah1, bh0[j], bh1[j]);
                #pragma unroll
                for (int j = 0; j < 4; j++) mma16h(accl[0][hb*4+j], ah0, bl0[j], bl1[j]);
                #pragma unroll
                for (int j = 0; j < 4; j++) mma16h(accl[1][hb*4+j], ah1, bl0[j], bl1[j]);
            }
        }
        __syncthreads();
    }

    #pragma unroll
    for (int mf = 0; mf < 2; mf++) {
        int mA = m0 + wm * 32 + mf * 16 + g;
        int mB = mA + 8;
        #pragma unroll
        for (int nf = 0; nf < 8; nf++) {
            float2 l0 = __half22float2(*reinterpret_cast<__half2*>(&accl[mf][nf].x));
            float2 l1 = __half22float2(*reinterpret_cast<__half2*>(&accl[mf][nf].y));
            float4 c = acc[mf][nf];
            c.x += l0.x; c.y += l0.y; c.z += l1.x; c.w += l1.y;
            int n = n0 + wn * 64 + nf * 8 + 2 * qd;
            *(float2*)(Outf + (size_t)mA * DMODEL + n) = make_float2(c.x, c.y);
            *(float2*)(Outf + (size_t)mB * DMODEL + n) = make_float2(c.z, c.w);
        }
    }
}

// ---------------------------------------------------------------------------
// Flash attention — PERSISTENT: grid=296 over 512 (q-tile, h, b) items.
// Per-item math identical to R12 (bitwise).
// S = Qh·(Kh+Kl) 2-term; PV 2-term (Ph·Vh + Ph·Vl).
// ---------------------------------------------------------------------------
#define ATTN_SMEM ((4608 + 2 * 9216) * 4)   // 92160 B

__global__ __launch_bounds__(256, 2)
void attn_p()
{
    extern __shared__ uint32_t sa[];

    const int tid  = threadIdx.x;
    const int lane = tid & 31;
    const int g    = lane >> 2;
    const int qd   = lane & 3;
    const int wq0  = (tid >> 5) * 16;

    const uint32_t SB = smem_u32(sa);
    const uint32_t QH = SB;

    const int arow = lane & 15, acol = (lane >> 4) * 4;
    const uint32_t q_off  = ((wq0 + arow) * 36 + acol) * 4;
    const uint32_t r_off0 = (lane * 36) * 4;
    const uint32_t r_off1 = r_off0 + 32 * 36 * 4;
    const uint32_t v_off = (((lane & 7) + ((lane >> 3) & 1) * 8) * 36
                            + (lane >> 4) * 4) * 4;

    for (int it = blockIdx.x; it < 512; it += NSM2) {
        const int q0 = (it & 15) * 128;
        const int h  = (it >> 4) & 15;
        const int b  = it >> 8;
        const size_t base32 = ((size_t)h * BATCH + b) * SEQ * 32;

        auto load_q = [&]() {
            #pragma unroll
            for (int t = 0; t < 4; t++) {
                int f = tid + t * 256;
                int row = f >> 3, ch = f & 7;
                uint32_t dst = SB + (uint32_t)(row * 36 + ch * 4) * 4;
                cp16(dst, g_Qh + base32 + (size_t)(q0 + row) * 32 + ch * 4);
            }
        };
        auto load_kv = [&](int kt, int bf) {
            uint32_t bb = SB + (uint32_t)(4608 + bf * 9216) * 4;
            int k0 = kt * 64;
            #pragma unroll
            for (int t = 0; t < 8; t++) {
                int f = tid + t * 256;
                int arr = f >> 9, gg = f & 511;
                int row = gg >> 3, ch = gg & 7;
                uint32_t dst = bb + (uint32_t)(arr * 2304 + row * 36 + ch * 4) * 4;
                const uint32_t* p =
                    (arr == 0) ? g_Kh : (arr == 1) ? g_Kl : (arr == 2) ? g_Vh : g_Vl;
                cp16(dst, p + base32 + (size_t)(k0 + row) * 32 + ch * 4);
            }
        };

        load_q();
        load_kv(0, 0);
        CP_COMMIT();

        float4 o[8];
        #pragma unroll
        for (int j = 0; j < 8; j++) o[j] = make_float4(0.f, 0.f, 0.f, 0.f);
        float mA = -1e30f, mB = -1e30f, lA = 0.f, lB = 0.f;

        for (int kt = 0; kt < SEQ / 64; kt++) {
            if (kt < 31) { load_kv(kt + 1, (kt + 1) & 1); CP_COMMIT(); CP_WAIT(1); }
            else         { CP_WAIT(0); }
            __syncthreads();

            const uint32_t KB = SB + (uint32_t)(4608 + (kt & 1) * 9216) * 4;
            const uint32_t KH = KB, KL = KB + 2304 * 4;
            const uint32_t VH = KB + 4608 * 4, VL = KB + 6912 * 4;

            float4 s[8];
            #pragma unroll
            for (int j = 0; j < 8; j++) s[j] = make_float4(0.f, 0.f, 0.f, 0.f);

            #pragma unroll
            for (int st = 0; st < 4; st++) {
                uint32_t sc = st * 32;
                uint32_t ah[4];
                ldsm_x4(ah, QH + q_off + sc);
                #pragma unroll
                for (int hb = 0; hb < 2; hb++) {
                    uint32_t boff = (hb ? r_off1 : r_off0) + sc;
                    uint32_t bh0[4], bh1[4], bl0[4], bl1[4];
                    ldsm_x4(bh0, KH + boff);
                    ldsm_x4(bh1, KH + boff + 16);
                    ldsm_x4(bl0, KL + boff);
                    ldsm_x4(bl1, KL + boff + 16);
                    #pragma unroll
                    for (int j = 0; j < 4; j++) mma16(s[hb*4+j], ah, bh0[j], bh1[j]);
                    #pragma unroll
                    for (int j = 0; j < 4; j++) mma16(s[hb*4+j], ah, bl0[j], bl1[j]);
                }
            }

            float mtA = -1e30f, mtB = -1e30f;
            #pragma unroll
            for (int nf = 0; nf < 8; nf++) {
                mtA = fmaxf(mtA, fmaxf(s[nf].x, s[nf].y));
                mtB = fmaxf(mtB, fmaxf(s[nf].z, s[nf].w));
            }
            mtA = fmaxf(mtA, __shfl_xor_sync(0xffffffffu, mtA, 1));
            mtA = fmaxf(mtA, __shfl_xor_sync(0xffffffffu, mtA, 2));
            mtB = fmaxf(mtB, __shfl_xor_sync(0xffffffffu, mtB, 1));
            mtB = fmaxf(mtB, __shfl_xor_sync(0xffffffffu, mtB, 2));

            float mnA = fmaxf(mA, mtA), mnB = fmaxf(mB, mtB);
            float alA = __expf(mA - mnA), alB = __expf(mB - mnB);
            float sumA = 0.f, sumB = 0.f;
            #pragma unroll
            for (int nf = 0; nf < 8; nf++) {
                s[nf].x = __expf(s[nf].x - mnA);
                s[nf].y = __expf(s[nf].y - mnA);
                s[nf].z = __expf(s[nf].z - mnB);
                s[nf].w = __expf(s[nf].w - mnB);
                sumA += s[nf].x + s[nf].y;
                sumB += s[nf].z + s[nf].w;
            }
            sumA += __shfl_xor_sync(0xffffffffu, sumA, 1);
            sumA += __shfl_xor_sync(0xffffffffu, sumA, 2);
            sumB += __shfl_xor_sync(0xffffffffu, sumB, 1);
            sumB += __shfl_xor_sync(0xffffffffu, sumB, 2);
            lA = lA * alA + sumA; mA = mnA;
            lB = lB * alB + sumB; mB = mnB;
            #pragma unroll
            for (int nf = 0; nf < 8; nf++) {
                o[nf].x *= alA; o[nf].y *= alA;
                o[nf].z *= alB; o[nf].w *= alB;
            }

            #pragma unroll
            for (int st = 0; st < 4; st++) {
                uint32_t pah[4];
                pah[0] = pack2(s[2*st].x,   s[2*st].y);
                pah[1] = pack2(s[2*st].z,   s[2*st].w);
                pah[2] = pack2(s[2*st+1].x, s[2*st+1].y);
                pah[3] = pack2(s[2*st+1].z, s[2*st+1].w);
                uint32_t stoff = (uint32_t)(st * 16 * 36) * 4;
                #pragma unroll
                for (int egp = 0; egp < 2; egp++) {
                    uint32_t e0 = (uint32_t)(egp * 2) * 32;
                    uint32_t vh0[4], vh1[4], vl0[4], vl1[4];
                    ldsm_x4t(vh0, VH + v_off + stoff + e0);
                    ldsm_x4t(vh1, VH + v_off + stoff + e0 + 32);
                    ldsm_x4t(vl0, VL + v_off + stoff + e0);
                    ldsm_x4t(vl1, VL + v_off + stoff + e0 + 32);
                    int nb = egp * 4;
                    mma16(o[nb+0], pah, vh0[0], vh0[1]);
                    mma16(o[nb+1], pah, vh0[2], vh0[3]);
                    mma16(o[nb+2], pah, vh1[0], vh1[1]);
                    mma16(o[nb+3], pah, vh1[2], vh1[3]);
                    mma16(o[nb+0], pah, vl0[0], vl0[1]);
                    mma16(o[nb+1], pah, vl0[2], vl0[3]);
                    mma16(o[nb+2], pah, vl1[0], vl1[1]);
                    mma16(o[nb+3], pah, vl1[2], vl1[3]);
                }
            }
            __syncthreads();
        }

        float invA = 1.f / lA, invB = 1.f / lB;
        int qA = q0 + wq0 + g, qB = qA + 8;
        #pragma unroll
        for (int nf = 0; nf < 8; nf++) {
            int pr = h * 32 + nf * 4 + qd;
            g_Hh[((size_t)b * SEQ + qA) * KPAIRS + pr] =
                pack2(o[nf].x * invA, o[nf].y * invA);
            g_Hh[((size_t)b * SEQ + qB) * KPAIRS + pr] =
                pack2(o[nf].z * invB, o[nf].w * invB);
        }
    }
}

// ---------------------------------------------------------------------------
extern "C" void kernel_launch(void* const* d_in, const int* in_sizes, int n_in,
                              void* d_out, int out_size)
{
    const float* q  = (const float*)d_in[0];
    const float* k  = (const float*)d_in[1];
    const float* v  = (const float*)d_in[2];
    const float* Wq = (const float*)d_in[3];
    const float* Wk = (const float*)d_in[4];
    const float* Wv = (const float*)d_in[5];
    const float* Wo = (const float*)d_in[6];
    float* out = (float*)d_out;

    cudaFuncSetAttribute(gemm_qkv, cudaFuncAttributeMaxDynamicSharedMemorySize, GEMM_SMEM);
    cudaFuncSetAttribute(gemm_out, cudaFuncAttributeMaxDynamicSharedMemorySize, GEMM_SMEM);
    cudaFuncSetAttribute(attn_p,   cudaFuncAttributeMaxDynamicSharedMemorySize, ATTN_SMEM);

    presplit_hi3  <<<dim3(NP / 256, 1, 3), 256>>>(q, k, v);
    presplit_wqkv3<<<dim3(WN / 256, 1, 3), 256>>>(Wq, Wk, Wv);
    presplit_wo   <<<WN / 256, 256>>>(Wo);

    gemm_qkv<<<NSM2, 256, GEMM_SMEM>>>();

    attn_p<<<NSM2, 256, ATTN_SMEM>>>();

    gemm_out<<<dim3(DMODEL / 128, MROWS / 128), 256, GEMM_SMEM>>>(out);
}

// round 14
// speedup vs baseline: 1.0970x; 1.0970x over previous
#include <cuda_runtime.h>
#include <cuda_fp16.h>
#include <stdint.h>

#define NHEADS 16
#define BATCH  2
#define SEQ    2048
#define DMODEL 1024
#define HID    64
#define MROWS  4096
#define KPAIRS 512          // DMODEL/2
#define NORM   0.125f
#define NP     (MROWS*KPAIRS)
#define WN     (DMODEL*KPAIRS)

// ---------------------------------------------------------------------------
// Global scratch. Inputs + Q + H are hi-only; K,V and weights are split.
// ---------------------------------------------------------------------------
__device__ uint32_t g_Xh[3u*NP];                  // inputs hi [which][m][kpair]
__device__ uint32_t g_Wh[4u*WN], g_Wl[4u*WN];     // weights hi/lo [which][n][kpair]
__device__ uint32_t g_Qh[NP];                     // [h][b][s][32 epairs] (hi only)
__device__ uint32_t g_Kh[NP], g_Kl[NP];
__device__ uint32_t g_Vh[NP], g_Vl[NP];
__device__ uint32_t g_Hh[NP];                     // attn out hi [b][s][512 pairs]

// ---------------------------------------------------------------------------
// helpers
// ---------------------------------------------------------------------------
__device__ __forceinline__ void split2(float x, float y, uint32_t& hi, uint32_t& lo) {
    __half hx = __float2half_rn(x), hy = __float2half_rn(y);
    __half2 H = __halves2half2(hx, hy);
    __half2 L = __floats2half2_rn(x - __half2float(hx), y - __half2float(hy));
    hi = *reinterpret_cast<uint32_t*>(&H);
    lo = *reinterpret_cast<uint32_t*>(&L);
}
__device__ __forceinline__ uint32_t pack2(float x, float y) {
    __half2 H = __floats2half2_rn(x, y);
    return *reinterpret_cast<uint32_t*>(&H);
}
__device__ __forceinline__ uint32_t smem_u32(const void* p) {
    return (uint32_t)__cvta_generic_to_shared(p);
}
__device__ __forceinline__ void ldsm_x4(uint32_t* r, uint32_t addr) {
    asm volatile("ldmatrix.sync.aligned.m8n8.x4.shared.b16 {%0,%1,%2,%3},[%4];"
        : "=r"(r[0]), "=r"(r[1]), "=r"(r[2]), "=r"(r[3]) : "r"(addr));
}
__device__ __forceinline__ void ldsm_x4t(uint32_t* r, uint32_t addr) {
    asm volatile("ldmatrix.sync.aligned.m8n8.x4.trans.shared.b16 {%0,%1,%2,%3},[%4];"
        : "=r"(r[0]), "=r"(r[1]), "=r"(r[2]), "=r"(r[3]) : "r"(addr));
}
// fp32-accumulate fp16 MMA
__device__ __forceinline__ void mma16(float4& d, const uint32_t* a,
                                      uint32_t b0, uint32_t b1) {
    asm volatile(
        "mma.sync.aligned.m16n8k16.row.col.f32.f16.f16.f32 "
        "{%0,%1,%2,%3},{%4,%5,%6,%7},{%8,%9},{%0,%1,%2,%3};"
        : "+f"(d.x), "+f"(d.y), "+f"(d.z), "+f"(d.w)
        : "r"(a[0]), "r"(a[1]), "r"(a[2]), "r"(a[3]), "r"(b0), "r"(b1));
}
// fp16-accumulate fp16 MMA — lo correction terms only
__device__ __forceinline__ void mma16h(uint2& d, const uint32_t* a,
                                       uint32_t b0, uint32_t b1) {
    asm volatile(
        "mma.sync.aligned.m16n8k16.row.col.f16.f16.f16.f16 "
        "{%0,%1},{%2,%3,%4,%5},{%6,%7},{%0,%1};"
        : "+r"(d.x), "+r"(d.y)
        : "r"(a[0]), "r"(a[1]), "r"(a[2]), "r"(a[3]), "r"(b0), "r"(b1));
}
__device__ __forceinline__ void cp16(uint32_t dst, const void* src) {
    asm volatile("cp.async.cg.shared.global [%0], [%1], 16;" :: "r"(dst), "l"(src));
}
#define CP_COMMIT() asm volatile("cp.async.commit_group;")
#define CP_WAIT(N)  asm volatile("cp.async.wait_group %0;" :: "n"(N))

// ---------------------------------------------------------------------------
// presplit kernels (vectorized / merged)
// ---------------------------------------------------------------------------
// Inputs: 4 pairs per thread (2x float4 in, uint4 out). Values identical.
__global__ void presplit_hi3(const float* __restrict__ s0,
                             const float* __restrict__ s1,
                             const float* __restrict__ s2) {
    int z = blockIdx.z;
    const float* src = (z == 0) ? s0 : (z == 1) ? s1 : s2;
    int i4 = blockIdx.x * 256 + threadIdx.x;     // index in groups of 4 pairs
    float4 a = ((const float4*)src)[i4 * 2];
    float4 b = ((const float4*)src)[i4 * 2 + 1];
    uint4 o;
    o.x = pack2(a.x, a.y); o.y = pack2(a.z, a.w);
    o.z = pack2(b.x, b.y); o.w = pack2(b.z, b.w);
    ((uint4*)(g_Xh + (size_t)z * NP))[i4] = o;
}
// Weights merged: z=0..2 -> Wq/Wk/Wv (layout [h][k][e] -> [n][p]); z=3 -> Wo
// ([k][n] -> [n][p]). 2 pairs per thread. Per-element math identical to R12.
__global__ void presplit_w(const float* __restrict__ W0,
                           const float* __restrict__ W1,
                           const float* __restrict__ W2,
                           const float* __restrict__ W3) {
    int z = blockIdx.z;
    int i2 = blockIdx.x * 256 + threadIdx.x;     // groups of 2 pairs
    int i = i2 * 2;
    int n = i >> 9, p = i & 511;                 // p, p+1 same n
    uint32_t hh0, ll0, hh1, ll1;
    if (z < 3) {
        const float* W = (z == 0) ? W0 : (z == 1) ? W1 : W2;
        float scale = (z == 0) ? NORM : 1.0f;
        int h = n >> 6, e = n & 63;
        const float* s = W + (size_t)h * DMODEL * HID + (size_t)(2 * p) * HID + e;
        split2(s[0] * scale,       s[HID] * scale,     hh0, ll0);
        split2(s[2 * HID] * scale, s[3 * HID] * scale, hh1, ll1);
    } else {
        split2(W3[(size_t)(2 * p) * DMODEL + n],
               W3[(size_t)(2 * p + 1) * DMODEL + n], hh0, ll0);
        split2(W3[(size_t)(2 * p + 2) * DMODEL + n],
               W3[(size_t)(2 * p + 3) * DMODEL + n], hh1, ll1);
    }
    uint32_t* dh = g_Wh + (size_t)z * WN + i;
    uint32_t* dl = g_Wl + (size_t)z * WN + i;
    *(uint2*)dh = make_uint2(hh0, hh1);
    *(uint2*)dl = make_uint2(ll0, ll1);
}

// ---------------------------------------------------------------------------
// QKV projection GEMM (merged z=0,1,2): hi term Ah·Bh fp32 acc; lo term
// Ah·Bl fp16 acc, merged after K loop. BM=BN=128, BK=64, 8 warps (4m x 2n),
// cp.async double-buffered. (R12 structure, classic grid.)
// ---------------------------------------------------------------------------
#define GEMM_SMEM (2 * 3 * 4608 * 4)   // 110592 B

__global__ __launch_bounds__(256, 2)
void gemm_qkv()
{
    extern __shared__ uint32_t sg[];   // [2][3][4608]

    const int z    = blockIdx.z;
    const int tid  = threadIdx.x;
    const int lane = tid & 31;
    const int wid  = tid >> 5;
    const int g    = lane >> 2;
    const int qd   = lane & 3;
    const int wm   = wid >> 1;
    const int wn   = wid & 1;
    const int m0   = blockIdx.y * 128;
    const int n0   = blockIdx.x * 128;

    const uint32_t* Ahg = g_Xh + (size_t)z * NP;
    const uint32_t* Bhg = g_Wh + (size_t)z * WN;
    const uint32_t* Blg = g_Wl + (size_t)z * WN;

    const uint32_t SB = smem_u32(sg);
    const int arow = lane & 15, acol = (lane >> 4) * 4;
    const uint32_t a_off0 = ((wm * 32 + arow) * 36 + acol) * 4;
    const uint32_t a_off1 = a_off0 + 16 * 36 * 4;
    const uint32_t b_off0 = ((wn * 64 + lane) * 36) * 4;
    const uint32_t b_off1 = b_off0 + 32 * 36 * 4;

    float4 acc[2][8];
    uint2  accl[2][8];
    #pragma unroll
    for (int i = 0; i < 2; i++)
        #pragma unroll
        for (int j = 0; j < 8; j++) {
            acc[i][j]  = make_float4(0.f, 0.f, 0.f, 0.f);
            accl[i][j] = make_uint2(0u, 0u);
        }

    auto load_tile = [&](int kt, int bf) {
        const uint32_t base = SB + (uint32_t)bf * 13824 * 4;
        int kp0 = kt * 32;
        #pragma unroll
        for (int t = 0; t < 12; t++) {
            int f = tid + t * 256;            // 0..3071
            int arr = f >> 10, gg = f & 1023;
            int row = gg >> 3, ch = gg & 7;
            uint32_t dst = base + (uint32_t)(arr * 4608 + row * 36 + ch * 4) * 4;
            const uint32_t* src =
                (arr == 0) ? Ahg + (size_t)(m0 + row) * KPAIRS + kp0 + ch * 4 :
                (arr == 1) ? Bhg + (size_t)(n0 + row) * KPAIRS + kp0 + ch * 4 :
                             Blg + (size_t)(n0 + row) * KPAIRS + kp0 + ch * 4;
            cp16(dst, src);
        }
    };

    load_tile(0, 0);
    CP_COMMIT();

    for (int kt = 0; kt < 16; kt++) {
        if (kt < 15) { load_tile(kt + 1, (kt + 1) & 1); CP_COMMIT(); CP_WAIT(1); }
        else         { CP_WAIT(0); }
        __syncthreads();

        const uint32_t base = SB + (uint32_t)(kt & 1) * 13824 * 4;
        const uint32_t AHB = base;
        const uint32_t BHB = base + 4608 * 4, BLB = base + 9216 * 4;

        #pragma unroll
        for (int s = 0; s < 4; s++) {
            uint32_t sc = s * 32;
            uint32_t ah0[4], ah1[4];
            ldsm_x4(ah0, AHB + a_off0 + sc);
            ldsm_x4(ah1, AHB + a_off1 + sc);
            #pragma unroll
            for (int hb = 0; hb < 2; hb++) {
                uint32_t boff = (hb ? b_off1 : b_off0) + sc;
                uint32_t bh0[4], bh1[4], bl0[4], bl1[4];
                ldsm_x4(bh0, BHB + boff);
                ldsm_x4(bh1, BHB + boff + 16);
                ldsm_x4(bl0, BLB + boff);
                ldsm_x4(bl1, BLB + boff + 16);
                #pragma unroll
                for (int j = 0; j < 4; j++) mma16(acc[0][hb*4+j], ah0, bh0[j], bh1[j]);
                #pragma unroll
                for (int j = 0; j < 4; j++) mma16(acc[1][hb*4+j], ah1, bh0[j], bh1[j]);
                #pragma unroll
                for (int j = 0; j < 4; j++) mma16h(accl[0][hb*4+j], ah0, bl0[j], bl1[j]);
                #pragma unroll
                for (int j = 0; j < 4; j++) mma16h(accl[1][hb*4+j], ah1, bl0[j], bl1[j]);
            }
        }
        __syncthreads();
    }

    // Merge lo (fp16) into hi (fp32); epilogue: Q hi-only; K,V split
    #pragma unroll
    for (int mf = 0; mf < 2; mf++) {
        int mA = m0 + wm * 32 + mf * 16 + g;
        int mB = mA + 8;
        #pragma unroll
        for (int nf = 0; nf < 8; nf++) {
            float2 l0 = __half22float2(*reinterpret_cast<__half2*>(&accl[mf][nf].x));
            float2 l1 = __half22float2(*reinterpret_cast<__half2*>(&accl[mf][nf].y));
            float4 c = acc[mf][nf];
            c.x += l0.x; c.y += l0.y; c.z += l1.x; c.w += l1.y;
            int head = (n0 >> 6) + wn;
            int pr   = nf * 4 + qd;
            int bA = mA >> 11, sA = mA & 2047;
            int bB = mB >> 11, sB = mB & 2047;
            size_t dA = (((size_t)head * BATCH + bA) * SEQ + sA) * 32 + pr;
            size_t dB = (((size_t)head * BATCH + bB) * SEQ + sB) * 32 + pr;
            if (z == 0) {
                g_Qh[dA] = pack2(c.x, c.y);
                g_Qh[dB] = pack2(c.z, c.w);
            } else {
                uint32_t* Oh = (z == 1) ? g_Kh : g_Vh;
                uint32_t* Ol = (z == 1) ? g_Kl : g_Vl;
                uint32_t hh, ll;
                split2(c.x, c.y, hh, ll);
                Oh[dA] = hh; Ol[dA] = ll;
                split2(c.z, c.w, hh, ll);
                Oh[dB] = hh; Ol[dB] = ll;
            }
        }
    }
}

// ---------------------------------------------------------------------------
// Output projection GEMM: hi term fp32 acc, lo term fp16 acc. BK=64.
// ---------------------------------------------------------------------------
__global__ __launch_bounds__(256, 2)
void gemm_out(float* __restrict__ Outf)
{
    extern __shared__ uint32_t sg[];   // [2][3][4608]

    const int tid  = threadIdx.x;
    const int lane = tid & 31;
    const int wid  = tid >> 5;
    const int g    = lane >> 2;
    const int qd   = lane & 3;
    const int wm   = wid >> 1;
    const int wn   = wid & 1;
    const int m0   = blockIdx.y * 128;
    const int n0   = blockIdx.x * 128;

    const uint32_t* Ahg = g_Hh;
    const uint32_t* Bhg = g_Wh + 3u * WN;
    const uint32_t* Blg = g_Wl + 3u * WN;

    const uint32_t SB = smem_u32(sg);
    const int arow = lane & 15, acol = (lane >> 4) * 4;
    const uint32_t a_off0 = ((wm * 32 + arow) * 36 + acol) * 4;
    const uint32_t a_off1 = a_off0 + 16 * 36 * 4;
    const uint32_t b_off0 = ((wn * 64 + lane) * 36) * 4;
    const uint32_t b_off1 = b_off0 + 32 * 36 * 4;

    float4 acc[2][8];
    uint2  accl[2][8];
    #pragma unroll
    for (int i = 0; i < 2; i++)
        #pragma unroll
        for (int j = 0; j < 8; j++) {
            acc[i][j]  = make_float4(0.f, 0.f, 0.f, 0.f);
            accl[i][j] = make_uint2(0u, 0u);
        }

    auto load_tile = [&](int kt, int bf) {
        const uint32_t base = SB + (uint32_t)bf * 13824 * 4;
        int kp0 = kt * 32;
        #pragma unroll
        for (int t = 0; t < 12; t++) {
            int f = tid + t * 256;
            int arr = f >> 10, gg = f & 1023;
            int row = gg >> 3, ch = gg & 7;
            uint32_t dst = base + (uint32_t)(arr * 4608 + row * 36 + ch * 4) * 4;
            const uint32_t* src =
                (arr == 0) ? Ahg + (size_t)(m0 + row) * KPAIRS + kp0 + ch * 4 :
                (arr == 1) ? Bhg + (size_t)(n0 + row) * KPAIRS + kp0 + ch * 4 :
                             Blg + (size_t)(n0 + row) * KPAIRS + kp0 + ch * 4;
            cp16(dst, src);
        }
    };

    load_tile(0, 0);
    CP_COMMIT();

    for (int kt = 0; kt < 16; kt++) {
        if (kt < 15) { load_tile(kt + 1, (kt + 1) & 1); CP_COMMIT(); CP_WAIT(1); }
        else         { CP_WAIT(0); }
        __syncthreads();

        const uint32_t base = SB + (uint32_t)(kt & 1) * 13824 * 4;
        const uint32_t AHB = base;
        const uint32_t BHB = base + 4608 * 4, BLB = base + 9216 * 4;

        #pragma unroll
        for (int s = 0; s < 4; s++) {
            uint32_t sc = s * 32;
            uint32_t ah0[4], ah1[4];
            ldsm_x4(ah0, AHB + a_off0 + sc);
            ldsm_x4(ah1, AHB + a_off1 + sc);
            #pragma unroll
            for (int hb = 0; hb < 2; hb++) {
                uint32_t boff = (hb ? b_off1 : b_off0) + sc;
                uint32_t bh0[4], bh1[4], bl0[4], bl1[4];
                ldsm_x4(bh0, BHB + boff);
                ldsm_x4(bh1, BHB + boff + 16);
                ldsm_x4(bl0, BLB + boff);
                ldsm_x4(bl1, BLB + boff + 16);
                #pragma unroll
                for (int j = 0; j < 4; j++) mma16(acc[0][hb*4+j], ah0, bh0[j], bh1[j]);
                #pragma unroll
                for (int j = 0; j < 4; j++) mma16(acc[1][hb*4+j], ah1, bh0[j], bh1[j]);
                #pragma unroll
                for (int j = 0; j < 4; j++) mma16h(accl[0][hb*4+j], ah0, bl0[j], bl1[j]);
                #pragma unroll
                for (int j = 0; j < 4; j++) mma16h(accl[1][hb*4+j], ah1, bl0[j], bl1[j]);
            }
        }
        __syncthreads();
    }

    #pragma unroll
    for (int mf = 0; mf < 2; mf++) {
        int mA = m0 + wm * 32 + mf * 16 + g;
        int mB = mA + 8;
        #pragma unroll
        for (int nf = 0; nf < 8; nf++) {
            float2 l0 = __half22float2(*reinterpret_cast<__half2*>(&accl[mf][nf].x));
            float2 l1 = __half22float2(*reinterpret_cast<__half2*>(&accl[mf][nf].y));
            float4 c = acc[mf][nf];
            c.x += l0.x; c.y += l0.y; c.z += l1.x; c.w += l1.y;
            int n = n0 + wn * 64 + nf * 8 + 2 * qd;
            *(float2*)(Outf + (size_t)mA * DMODEL + n) = make_float2(c.x, c.y);
            *(float2*)(Outf + (size_t)mB * DMODEL + n) = make_float2(c.z, c.w);
        }
    }
}

// ---------------------------------------------------------------------------
// Flash attention — R12 structure (classic grid, bitwise-identical numerics).
// S = Qh·(Kh+Kl) 2-term; PV 2-term (Ph·Vh + Ph·Vl).
// ---------------------------------------------------------------------------
#define ATTN_SMEM ((4608 + 2 * 9216) * 4)   // 92160 B

__global__ __launch_bounds__(256, 2)
void attn_p()
{
    extern __shared__ uint32_t sa[];

    const int tid  = threadIdx.x;
    const int lane = tid & 31;
    const int g    = lane >> 2;
    const int qd   = lane & 3;
    const int wq0  = (tid >> 5) * 16;

    const int q0 = blockIdx.x * 128;
    const int h  = blockIdx.y;
    const int b  = blockIdx.z;
    const size_t base32 = ((size_t)h * BATCH + b) * SEQ * 32;

    const uint32_t SB = smem_u32(sa);
    const uint32_t QH = SB;

    const int arow = lane & 15, acol = (lane >> 4) * 4;
    const uint32_t q_off  = ((wq0 + arow) * 36 + acol) * 4;
    const uint32_t r_off0 = (lane * 36) * 4;
    const uint32_t r_off1 = r_off0 + 32 * 36 * 4;
    const uint32_t v_off = (((lane & 7) + ((lane >> 3) & 1) * 8) * 36
                            + (lane >> 4) * 4) * 4;

    auto load_q = [&]() {
        #pragma unroll
        for (int t = 0; t < 4; t++) {
            int f = tid + t * 256;
            int row = f >> 3, ch = f & 7;
            uint32_t dst = SB + (uint32_t)(row * 36 + ch * 4) * 4;
            cp16(dst, g_Qh + base32 + (size_t)(q0 + row) * 32 + ch * 4);
        }
    };
    auto load_kv = [&](int kt, int bf) {
        uint32_t bb = SB + (uint32_t)(4608 + bf * 9216) * 4;
        int k0 = kt * 64;
        #pragma unroll
        for (int t = 0; t < 8; t++) {
            int f = tid + t * 256;
            int arr = f >> 9, gg = f & 511;
            int row = gg >> 3, ch = gg & 7;
            uint32_t dst = bb + (uint32_t)(arr * 2304 + row * 36 + ch * 4) * 4;
            const uint32_t* p =
                (arr == 0) ? g_Kh : (arr == 1) ? g_Kl : (arr == 2) ? g_Vh : g_Vl;
            cp16(dst, p + base32 + (size_t)(k0 + row) * 32 + ch * 4);
        }
    };

    load_q();
    load_kv(0, 0);
    CP_COMMIT();

    float4 o[8];
    #pragma unroll
    for (int j = 0; j < 8; j++) o[j] = make_float4(0.f, 0.f, 0.f, 0.f);
    float mA = -1e30f, mB = -1e30f, lA = 0.f, lB = 0.f;

    for (int kt = 0; kt < SEQ / 64; kt++) {
        if (kt < 31) { load_kv(kt + 1, (kt + 1) & 1); CP_COMMIT(); CP_WAIT(1); }
        else         { CP_WAIT(0); }
        __syncthreads();

        const uint32_t KB = SB + (uint32_t)(4608 + (kt & 1) * 9216) * 4;
        const uint32_t KH = KB, KL = KB + 2304 * 4;
        const uint32_t VH = KB + 4608 * 4, VL = KB + 6912 * 4;

        float4 s[8];
        #pragma unroll
        for (int j = 0; j < 8; j++) s[j] = make_float4(0.f, 0.f, 0.f, 0.f);

        #pragma unroll
        for (int st = 0; st < 4; st++) {
            uint32_t sc = st * 32;
            uint32_t ah[4];
            ldsm_x4(ah, QH + q_off + sc);
            #pragma unroll
            for (int hb = 0; hb < 2; hb++) {
                uint32_t boff = (hb ? r_off1 : r_off0) + sc;
                uint32_t bh0[4], bh1[4], bl0[4], bl1[4];
                ldsm_x4(bh0, KH + boff);
                ldsm_x4(bh1, KH + boff + 16);
                ldsm_x4(bl0, KL + boff);
                ldsm_x4(bl1, KL + boff + 16);
                #pragma unroll
                for (int j = 0; j < 4; j++) mma16(s[hb*4+j], ah, bh0[j], bh1[j]);
                #pragma unroll
                for (int j = 0; j < 4; j++) mma16(s[hb*4+j], ah, bl0[j], bl1[j]);
            }
        }

        float mtA = -1e30f, mtB = -1e30f;
        #pragma unroll
        for (int nf = 0; nf < 8; nf++) {
            mtA = fmaxf(mtA, fmaxf(s[nf].x, s[nf].y));
            mtB = fmaxf(mtB, fmaxf(s[nf].z, s[nf].w));
        }
        mtA = fmaxf(mtA, __shfl_xor_sync(0xffffffffu, mtA, 1));
        mtA = fmaxf(mtA, __shfl_xor_sync(0xffffffffu, mtA, 2));
        mtB = fmaxf(mtB, __shfl_xor_sync(0xffffffffu, mtB, 1));
        mtB = fmaxf(mtB, __shfl_xor_sync(0xffffffffu, mtB, 2));

        float mnA = fmaxf(mA, mtA), mnB = fmaxf(mB, mtB);
        float alA = __expf(mA - mnA), alB = __expf(mB - mnB);
        float sumA = 0.f, sumB = 0.f;
        #pragma unroll
        for (int nf = 0; nf < 8; nf++) {
            s[nf].x = __expf(s[nf].x - mnA);
            s[nf].y = __expf(s[nf].y - mnA);
            s[nf].z = __expf(s[nf].z - mnB);
            s[nf].w = __expf(s[nf].w - mnB);
            sumA += s[nf].x + s[nf].y;
            sumB += s[nf].z + s[nf].w;
        }
        sumA += __shfl_xor_sync(0xffffffffu, sumA, 1);
        sumA += __shfl_xor_sync(0xffffffffu, sumA, 2);
        sumB += __shfl_xor_sync(0xffffffffu, sumB, 1);
        sumB += __shfl_xor_sync(0xffffffffu, sumB, 2);
        lA = lA * alA + sumA; mA = mnA;
        lB = lB * alB + sumB; mB = mnB;
        #pragma unroll
        for (int nf = 0; nf < 8; nf++) {
            o[nf].x *= alA; o[nf].y *= alA;
            o[nf].z *= alB; o[nf].w *= alB;
        }

        #pragma unroll
        for (int st = 0; st < 4; st++) {
            uint32_t pah[4];
            pah[0] = pack2(s[2*st].x,   s[2*st].y);
            pah[1] = pack2(s[2*st].z,   s[2*st].w);
            pah[2] = pack2(s[2*st+1].x, s[2*st+1].y);
            pah[3] = pack2(s[2*st+1].z, s[2*st+1].w);
            uint32_t stoff = (uint32_t)(st * 16 * 36) * 4;
            #pragma unroll
            for (int egp = 0; egp < 2; egp++) {
                uint32_t e0 = (uint32_t)(egp * 2) * 32;
                uint32_t vh0[4], vh1[4], vl0[4], vl1[4];
                ldsm_x4t(vh0, VH + v_off + stoff + e0);
                ldsm_x4t(vh1, VH + v_off + stoff + e0 + 32);
                ldsm_x4t(vl0, VL + v_off + stoff + e0);
                ldsm_x4t(vl1, VL + v_off + stoff + e0 + 32);
                int nb = egp * 4;
                mma16(o[nb+0], pah, vh0[0], vh0[1]);
                mma16(o[nb+1], pah, vh0[2], vh0[3]);
                mma16(o[nb+2], pah, vh1[0], vh1[1]);
                mma16(o[nb+3], pah, vh1[2], vh1[3]);
                mma16(o[nb+0], pah, vl0[0], vl0[1]);
                mma16(o[nb+1], pah, vl0[2], vl0[3]);
                mma16(o[nb+2], pah, vl1[0], vl1[1]);
                mma16(o[nb+3], pah, vl1[2], vl1[3]);
            }
        }
        __syncthreads();
    }

    float invA = 1.f / lA, invB = 1.f / lB;
    int qA = q0 + wq0 + g, qB = qA + 8;
    #pragma unroll
    for (int nf = 0; nf < 8; nf++) {
        int pr = h * 32 + nf * 4 + qd;
        g_Hh[((size_t)b * SEQ + qA) * KPAIRS + pr] =
            pack2(o[nf].x * invA, o[nf].y * invA);
        g_Hh[((size_t)b * SEQ + qB) * KPAIRS + pr] =
            pack2(o[nf].z * invB, o[nf].w * invB);
    }
}

// ---------------------------------------------------------------------------
extern "C" void kernel_launch(void* const* d_in, const int* in_sizes, int n_in,
                              void* d_out, int out_size)
{
    const float* q  = (const float*)d_in[0];
    const float* k  = (const float*)d_in[1];
    const float* v  = (const float*)d_in[2];
    const float* Wq = (const float*)d_in[3];
    const float* Wk = (const float*)d_in[4];
    const float* Wv = (const float*)d_in[5];
    const float* Wo = (const float*)d_in[6];
    float* out = (float*)d_out;

    cudaFuncSetAttribute(gemm_qkv, cudaFuncAttributeMaxDynamicSharedMemorySize, GEMM_SMEM);
    cudaFuncSetAttribute(gemm_out, cudaFuncAttributeMaxDynamicSharedMemorySize, GEMM_SMEM);
    cudaFuncSetAttribute(attn_p,   cudaFuncAttributeMaxDynamicSharedMemorySize, ATTN_SMEM);

    presplit_hi3<<<dim3(NP / 1024, 1, 3), 256>>>(q, k, v);
    presplit_w  <<<dim3(WN / 512, 1, 4), 256>>>(Wq, Wk, Wv, Wo);

    gemm_qkv<<<dim3(DMODEL / 128, MROWS / 128, 3), 256, GEMM_SMEM>>>();

    attn_p<<<dim3(SEQ / 128, NHEADS, BATCH), 256, ATTN_SMEM>>>();

    gemm_out<<<dim3(DMODEL / 128, MROWS / 128), 256, GEMM_SMEM>>>(out);
}

// round 15
// speedup vs baseline: 1.1019x; 1.0044x over previous
#include <cuda_runtime.h>
#include <cuda_fp16.h>
#include <stdint.h>

#define NHEADS 16
#define BATCH  2
#define SEQ    2048
#define DMODEL 1024
#define HID    64
#define MROWS  4096
#define KPAIRS 512          // DMODEL/2
#define NORM   0.125f
#define NP     (MROWS*KPAIRS)
#define WN     (DMODEL*KPAIRS)

// ---------------------------------------------------------------------------
// Global scratch. Inputs + Q + H are hi-only; K,V and weights are split.
// ---------------------------------------------------------------------------
__device__ uint32_t g_Xh[3u*NP];                  // inputs hi [which][m][kpair]
__device__ uint32_t g_Wh[4u*WN], g_Wl[4u*WN];     // weights hi/lo [which][n][kpair]
__device__ uint32_t g_Qh[NP];                     // [h][b][s][32 epairs] (hi only)
__device__ uint32_t g_Kh[NP], g_Kl[NP];
__device__ uint32_t g_Vh[NP], g_Vl[NP];
__device__ uint32_t g_Hh[NP];                     // attn out hi [b][s][512 pairs]

// ---------------------------------------------------------------------------
// helpers
// ---------------------------------------------------------------------------
__device__ __forceinline__ void split2(float x, float y, uint32_t& hi, uint32_t& lo) {
    __half hx = __float2half_rn(x), hy = __float2half_rn(y);
    __half2 H = __halves2half2(hx, hy);
    __half2 L = __floats2half2_rn(x - __half2float(hx), y - __half2float(hy));
    hi = *reinterpret_cast<uint32_t*>(&H);
    lo = *reinterpret_cast<uint32_t*>(&L);
}
__device__ __forceinline__ uint32_t pack2(float x, float y) {
    __half2 H = __floats2half2_rn(x, y);
    return *reinterpret_cast<uint32_t*>(&H);
}
__device__ __forceinline__ uint32_t smem_u32(const void* p) {
    return (uint32_t)__cvta_generic_to_shared(p);
}
__device__ __forceinline__ void ldsm_x4(uint32_t* r, uint32_t addr) {
    asm volatile("ldmatrix.sync.aligned.m8n8.x4.shared.b16 {%0,%1,%2,%3},[%4];"
        : "=r"(r[0]), "=r"(r[1]), "=r"(r[2]), "=r"(r[3]) : "r"(addr));
}
__device__ __forceinline__ void ldsm_x4t(uint32_t* r, uint32_t addr) {
    asm volatile("ldmatrix.sync.aligned.m8n8.x4.trans.shared.b16 {%0,%1,%2,%3},[%4];"
        : "=r"(r[0]), "=r"(r[1]), "=r"(r[2]), "=r"(r[3]) : "r"(addr));
}
// fp32-accumulate fp16 MMA
__device__ __forceinline__ void mma16(float4& d, const uint32_t* a,
                                      uint32_t b0, uint32_t b1) {
    asm volatile(
        "mma.sync.aligned.m16n8k16.row.col.f32.f16.f16.f32 "
        "{%0,%1,%2,%3},{%4,%5,%6,%7},{%8,%9},{%0,%1,%2,%3};"
        : "+f"(d.x), "+f"(d.y), "+f"(d.z), "+f"(d.w)
        : "r"(a[0]), "r"(a[1]), "r"(a[2]), "r"(a[3]), "r"(b0), "r"(b1));
}
// fp16-accumulate fp16 MMA — lo correction terms only
__device__ __forceinline__ void mma16h(uint2& d, const uint32_t* a,
                                       uint32_t b0, uint32_t b1) {
    asm volatile(
        "mma.sync.aligned.m16n8k16.row.col.f16.f16.f16.f16 "
        "{%0,%1},{%2,%3,%4,%5},{%6,%7},{%0,%1};"
        : "+r"(d.x), "+r"(d.y)
        : "r"(a[0]), "r"(a[1]), "r"(a[2]), "r"(a[3]), "r"(b0), "r"(b1));
}
__device__ __forceinline__ void cp16(uint32_t dst, const void* src) {
    asm volatile("cp.async.cg.shared.global [%0], [%1], 16;" :: "r"(dst), "l"(src));
}
#define CP_COMMIT() asm volatile("cp.async.commit_group;")
#define CP_WAIT(N)  asm volatile("cp.async.wait_group %0;" :: "n"(N))

// ---------------------------------------------------------------------------
// Presplit — single merged launch. z=0..2: inputs q/k/v (4 pairs/thread,
// vectorized, hi-only). z=3..6: weights Wq/Wk/Wv (scaled, [h][k][e]->[n][p])
// and Wo ([k][n]->[n][p]), 2 pairs/thread, hi/lo split.
// Per-element arithmetic identical to R14 (bitwise outputs).
// ---------------------------------------------------------------------------
__global__ void presplit_all(const float* __restrict__ q,
                             const float* __restrict__ k,
                             const float* __restrict__ v,
                             const float* __restrict__ W0,
                             const float* __restrict__ W1,
                             const float* __restrict__ W2,
                             const float* __restrict__ W3) {
    int z = blockIdx.z;
    if (z < 3) {
        const float* src = (z == 0) ? q : (z == 1) ? k : v;
        int i4 = blockIdx.x * 256 + threadIdx.x;     // groups of 4 pairs
        float4 a = ((const float4*)src)[i4 * 2];
        float4 b = ((const float4*)src)[i4 * 2 + 1];
        uint4 o;
        o.x = pack2(a.x, a.y); o.y = pack2(a.z, a.w);
        o.z = pack2(b.x, b.y); o.w = pack2(b.z, b.w);
        ((uint4*)(g_Xh + (size_t)z * NP))[i4] = o;
    } else {
        if (blockIdx.x >= WN / 512) return;          // weights need half the blocks
        int w = z - 3;
        int i2 = blockIdx.x * 256 + threadIdx.x;     // groups of 2 pairs
        int i = i2 * 2;
        int n = i >> 9, p = i & 511;
        uint32_t hh0, ll0, hh1, ll1;
        if (w < 3) {
            const float* W = (w == 0) ? W0 : (w == 1) ? W1 : W2;
            float scale = (w == 0) ? NORM : 1.0f;
            int h = n >> 6, e = n & 63;
            const float* s = W + (size_t)h * DMODEL * HID + (size_t)(2 * p) * HID + e;
            split2(s[0] * scale,       s[HID] * scale,     hh0, ll0);
            split2(s[2 * HID] * scale, s[3 * HID] * scale, hh1, ll1);
        } else {
            split2(W3[(size_t)(2 * p) * DMODEL + n],
                   W3[(size_t)(2 * p + 1) * DMODEL + n], hh0, ll0);
            split2(W3[(size_t)(2 * p + 2) * DMODEL + n],
                   W3[(size_t)(2 * p + 3) * DMODEL + n], hh1, ll1);
        }
        uint32_t* dh = g_Wh + (size_t)w * WN + i;
        uint32_t* dl = g_Wl + (size_t)w * WN + i;
        *(uint2*)dh = make_uint2(hh0, hh1);
        *(uint2*)dl = make_uint2(ll0, ll1);
    }
}

// ---------------------------------------------------------------------------
// QKV projection GEMM (merged z=0,1,2): hi term Ah·Bh fp32 acc; lo term
// Ah·Bl fp16 acc, merged after K loop. BM=BN=128, BK=64, 8 warps (4m x 2n),
// cp.async double-buffered. (Identical to R14.)
// ---------------------------------------------------------------------------
#define GEMM_SMEM (2 * 3 * 4608 * 4)   // 110592 B

__global__ __launch_bounds__(256, 2)
void gemm_qkv()
{
    extern __shared__ uint32_t sg[];   // [2][3][4608]

    const int z    = blockIdx.z;
    const int tid  = threadIdx.x;
    const int lane = tid & 31;
    const int wid  = tid >> 5;
    const int g    = lane >> 2;
    const int qd   = lane & 3;
    const int wm   = wid >> 1;
    const int wn   = wid & 1;
    const int m0   = blockIdx.y * 128;
    const int n0   = blockIdx.x * 128;

    const uint32_t* Ahg = g_Xh + (size_t)z * NP;
    const uint32_t* Bhg = g_Wh + (size_t)z * WN;
    const uint32_t* Blg = g_Wl + (size_t)z * WN;

    const uint32_t SB = smem_u32(sg);
    const int arow = lane & 15, acol = (lane >> 4) * 4;
    const uint32_t a_off0 = ((wm * 32 + arow) * 36 + acol) * 4;
    const uint32_t a_off1 = a_off0 + 16 * 36 * 4;
    const uint32_t b_off0 = ((wn * 64 + lane) * 36) * 4;
    const uint32_t b_off1 = b_off0 + 32 * 36 * 4;

    float4 acc[2][8];
    uint2  accl[2][8];
    #pragma unroll
    for (int i = 0; i < 2; i++)
        #pragma unroll
        for (int j = 0; j < 8; j++) {
            acc[i][j]  = make_float4(0.f, 0.f, 0.f, 0.f);
            accl[i][j] = make_uint2(0u, 0u);
        }

    auto load_tile = [&](int kt, int bf) {
        const uint32_t base = SB + (uint32_t)bf * 13824 * 4;
        int kp0 = kt * 32;
        #pragma unroll
        for (int t = 0; t < 12; t++) {
            int f = tid + t * 256;            // 0..3071
            int arr = f >> 10, gg = f & 1023;
            int row = gg >> 3, ch = gg & 7;
            uint32_t dst = base + (uint32_t)(arr * 4608 + row * 36 + ch * 4) * 4;
            const uint32_t* src =
                (arr == 0) ? Ahg + (size_t)(m0 + row) * KPAIRS + kp0 + ch * 4 :
                (arr == 1) ? Bhg + (size_t)(n0 + row) * KPAIRS + kp0 + ch * 4 :
                             Blg + (size_t)(n0 + row) * KPAIRS + kp0 + ch * 4;
            cp16(dst, src);
        }
    };

    load_tile(0, 0);
    CP_COMMIT();

    for (int kt = 0; kt < 16; kt++) {
        if (kt < 15) { load_tile(kt + 1, (kt + 1) & 1); CP_COMMIT(); CP_WAIT(1); }
        else         { CP_WAIT(0); }
        __syncthreads();

        const uint32_t base = SB + (uint32_t)(kt & 1) * 13824 * 4;
        const uint32_t AHB = base;
        const uint32_t BHB = base + 4608 * 4, BLB = base + 9216 * 4;

        #pragma unroll
        for (int s = 0; s < 4; s++) {
            uint32_t sc = s * 32;
            uint32_t ah0[4], ah1[4];
            ldsm_x4(ah0, AHB + a_off0 + sc);
            ldsm_x4(ah1, AHB + a_off1 + sc);
            #pragma unroll
            for (int hb = 0; hb < 2; hb++) {
                uint32_t boff = (hb ? b_off1 : b_off0) + sc;
                uint32_t bh0[4], bh1[4], bl0[4], bl1[4];
                ldsm_x4(bh0, BHB + boff);
                ldsm_x4(bh1, BHB + boff + 16);
                ldsm_x4(bl0, BLB + boff);
                ldsm_x4(bl1, BLB + boff + 16);
                #pragma unroll
                for (int j = 0; j < 4; j++) mma16(acc[0][hb*4+j], ah0, bh0[j], bh1[j]);
                #pragma unroll
                for (int j = 0; j < 4; j++) mma16(acc[1][hb*4+j], ah1, bh0[j], bh1[j]);
                #pragma unroll
                for (int j = 0; j < 4; j++) mma16h(accl[0][hb*4+j], ah0, bl0[j], bl1[j]);
                #pragma unroll
                for (int j = 0; j < 4; j++) mma16h(accl[1][hb*4+j], ah1, bl0[j], bl1[j]);
            }
        }
        __syncthreads();
    }

    // Merge lo (fp16) into hi (fp32); epilogue: Q hi-only; K,V split
    #pragma unroll
    for (int mf = 0; mf < 2; mf++) {
        int mA = m0 + wm * 32 + mf * 16 + g;
        int mB = mA + 8;
        #pragma unroll
        for (int nf = 0; nf < 8; nf++) {
            float2 l0 = __half22float2(*reinterpret_cast<__half2*>(&accl[mf][nf].x));
            float2 l1 = __half22float2(*reinterpret_cast<__half2*>(&accl[mf][nf].y));
            float4 c = acc[mf][nf];
            c.x += l0.x; c.y += l0.y; c.z += l1.x; c.w += l1.y;
            int head = (n0 >> 6) + wn;
            int pr   = nf * 4 + qd;
            int bA = mA >> 11, sA = mA & 2047;
            int bB = mB >> 11, sB = mB & 2047;
            size_t dA = (((size_t)head * BATCH + bA) * SEQ + sA) * 32 + pr;
            size_t dB = (((size_t)head * BATCH + bB) * SEQ + sB) * 32 + pr;
            if (z == 0) {
                g_Qh[dA] = pack2(c.x, c.y);
                g_Qh[dB] = pack2(c.z, c.w);
            } else {
                uint32_t* Oh = (z == 1) ? g_Kh : g_Vh;
                uint32_t* Ol = (z == 1) ? g_Kl : g_Vl;
                uint32_t hh, ll;
                split2(c.x, c.y, hh, ll);
                Oh[dA] = hh; Ol[dA] = ll;
                split2(c.z, c.w, hh, ll);
                Oh[dB] = hh; Ol[dB] = ll;
            }
        }
    }
}

// ---------------------------------------------------------------------------
// Output projection GEMM: hi term fp32 acc, lo term fp16 acc. BK=64.
// (Identical to R14.)
// ---------------------------------------------------------------------------
__global__ __launch_bounds__(256, 2)
void gemm_out(float* __restrict__ Outf)
{
    extern __shared__ uint32_t sg[];   // [2][3][4608]

    const int tid  = threadIdx.x;
    const int lane = tid & 31;
    const int wid  = tid >> 5;
    const int g    = lane >> 2;
    const int qd   = lane & 3;
    const int wm   = wid >> 1;
    const int wn   = wid & 1;
    const int m0   = blockIdx.y * 128;
    const int n0   = blockIdx.x * 128;

    const uint32_t* Ahg = g_Hh;
    const uint32_t* Bhg = g_Wh + 3u * WN;
    const uint32_t* Blg = g_Wl + 3u * WN;

    const uint32_t SB = smem_u32(sg);
    const int arow = lane & 15, acol = (lane >> 4) * 4;
    const uint32_t a_off0 = ((wm * 32 + arow) * 36 + acol) * 4;
    const uint32_t a_off1 = a_off0 + 16 * 36 * 4;
    const uint32_t b_off0 = ((wn * 64 + lane) * 36) * 4;
    const uint32_t b_off1 = b_off0 + 32 * 36 * 4;

    float4 acc[2][8];
    uint2  accl[2][8];
    #pragma unroll
    for (int i = 0; i < 2; i++)
        #pragma unroll
        for (int j = 0; j < 8; j++) {
            acc[i][j]  = make_float4(0.f, 0.f, 0.f, 0.f);
            accl[i][j] = make_uint2(0u, 0u);
        }

    auto load_tile = [&](int kt, int bf) {
        const uint32_t base = SB + (uint32_t)bf * 13824 * 4;
        int kp0 = kt * 32;
        #pragma unroll
        for (int t = 0; t < 12; t++) {
            int f = tid + t * 256;
            int arr = f >> 10, gg = f & 1023;
            int row = gg >> 3, ch = gg & 7;
            uint32_t dst = base + (uint32_t)(arr * 4608 + row * 36 + ch * 4) * 4;
            const uint32_t* src =
                (arr == 0) ? Ahg + (size_t)(m0 + row) * KPAIRS + kp0 + ch * 4 :
                (arr == 1) ? Bhg + (size_t)(n0 + row) * KPAIRS + kp0 + ch * 4 :
                             Blg + (size_t)(n0 + row) * KPAIRS + kp0 + ch * 4;
            cp16(dst, src);
        }
    };

    load_tile(0, 0);
    CP_COMMIT();

    for (int kt = 0; kt < 16; kt++) {
        if (kt < 15) { load_tile(kt + 1, (kt + 1) & 1); CP_COMMIT(); CP_WAIT(1); }
        else         { CP_WAIT(0); }
        __syncthreads();

        const uint32_t base = SB + (uint32_t)(kt & 1) * 13824 * 4;
        const uint32_t AHB = base;
        const uint32_t BHB = base + 4608 * 4, BLB = base + 9216 * 4;

        #pragma unroll
        for (int s = 0; s < 4; s++) {
            uint32_t sc = s * 32;
            uint32_t ah0[4], ah1[4];
            ldsm_x4(ah0, AHB + a_off0 + sc);
            ldsm_x4(ah1, AHB + a_off1 + sc);
            #pragma unroll
            for (int hb = 0; hb < 2; hb++) {
                uint32_t boff = (hb ? b_off1 : b_off0) + sc;
                uint32_t bh0[4], bh1[4], bl0[4], bl1[4];
                ldsm_x4(bh0, BHB + boff);
                ldsm_x4(bh1, BHB + boff + 16);
                ldsm_x4(bl0, BLB + boff);
                ldsm_x4(bl1, BLB + boff + 16);
                #pragma unroll
                for (int j = 0; j < 4; j++) mma16(acc[0][hb*4+j], ah0, bh0[j], bh1[j]);
                #pragma unroll
                for (int j = 0; j < 4; j++) mma16(acc[1][hb*4+j], ah1, bh0[j], bh1[j]);
                #pragma unroll
                for (int j = 0; j < 4; j++) mma16h(accl[0][hb*4+j], ah0, bl0[j], bl1[j]);
                #pragma unroll
                for (int j = 0; j < 4; j++) mma16h(accl[1][hb*4+j], ah1, bl0[j], bl1[j]);
            }
        }
        __syncthreads();
    }

    #pragma unroll
    for (int mf = 0; mf < 2; mf++) {
        int mA = m0 + wm * 32 + mf * 16 + g;
        int mB = mA + 8;
        #pragma unroll
        for (int nf = 0; nf < 8; nf++) {
            float2 l0 = __half22float2(*reinterpret_cast<__half2*>(&accl[mf][nf].x));
            float2 l1 = __half22float2(*reinterpret_cast<__half2*>(&accl[mf][nf].y));
            float4 c = acc[mf][nf];
            c.x += l0.x; c.y += l0.y; c.z += l1.x; c.w += l1.y;
            int n = n0 + wn * 64 + nf * 8 + 2 * qd;
            *(float2*)(Outf + (size_t)mA * DMODEL + n) = make_float2(c.x, c.y);
            *(float2*)(Outf + (size_t)mB * DMODEL + n) = make_float2(c.z, c.w);
        }
    }
}

// ---------------------------------------------------------------------------
// Flash attention — identical to R14 (bitwise numerics).
// S = Qh·(Kh+Kl) 2-term; PV 2-term (Ph·Vh + Ph·Vl).
// ---------------------------------------------------------------------------
#define ATTN_SMEM ((4608 + 2 * 9216) * 4)   // 92160 B

__global__ __launch_bounds__(256, 2)
void attn_p()
{
    extern __shared__ uint32_t sa[];

    const int tid  = threadIdx.x;
    const int lane = tid & 31;
    const int g    = lane >> 2;
    const int qd   = lane & 3;
    const int wq0  = (tid >> 5) * 16;

    const int q0 = blockIdx.x * 128;
    const int h  = blockIdx.y;
    const int b  = blockIdx.z;
    const size_t base32 = ((size_t)h * BATCH + b) * SEQ * 32;

    const uint32_t SB = smem_u32(sa);
    const uint32_t QH = SB;

    const int arow = lane & 15, acol = (lane >> 4) * 4;
    const uint32_t q_off  = ((wq0 + arow) * 36 + acol) * 4;
    const uint32_t r_off0 = (lane * 36) * 4;
    const uint32_t r_off1 = r_off0 + 32 * 36 * 4;
    const uint32_t v_off = (((lane & 7) + ((lane >> 3) & 1) * 8) * 36
                            + (lane >> 4) * 4) * 4;

    auto load_q = [&]() {
        #pragma unroll
        for (int t = 0; t < 4; t++) {
            int f = tid + t * 256;
            int row = f >> 3, ch = f & 7;
            uint32_t dst = SB + (uint32_t)(row * 36 + ch * 4) * 4;
            cp16(dst, g_Qh + base32 + (size_t)(q0 + row) * 32 + ch * 4);
        }
    };
    auto load_kv = [&](int kt, int bf) {
        uint32_t bb = SB + (uint32_t)(4608 + bf * 9216) * 4;
        int k0 = kt * 64;
        #pragma unroll
        for (int t = 0; t < 8; t++) {
            int f = tid + t * 256;
            int arr = f >> 9, gg = f & 511;
            int row = gg >> 3, ch = gg & 7;
            uint32_t dst = bb + (uint32_t)(arr * 2304 + row * 36 + ch * 4) * 4;
            const uint32_t* p =
                (arr == 0) ? g_Kh : (arr == 1) ? g_Kl : (arr == 2) ? g_Vh : g_Vl;
            cp16(dst, p + base32 + (size_t)(k0 + row) * 32 + ch * 4);
        }
    };

    load_q();
    load_kv(0, 0);
    CP_COMMIT();

    float4 o[8];
    #pragma unroll
    for (int j = 0; j < 8; j++) o[j] = make_float4(0.f, 0.f, 0.f, 0.f);
    float mA = -1e30f, mB = -1e30f, lA = 0.f, lB = 0.f;

    for (int kt = 0; kt < SEQ / 64; kt++) {
        if (kt < 31) { load_kv(kt + 1, (kt + 1) & 1); CP_COMMIT(); CP_WAIT(1); }
        else         { CP_WAIT(0); }
        __syncthreads();

        const uint32_t KB = SB + (uint32_t)(4608 + (kt & 1) * 9216) * 4;
        const uint32_t KH = KB, KL = KB + 2304 * 4;
        const uint32_t VH = KB + 4608 * 4, VL = KB + 6912 * 4;

        float4 s[8];
        #pragma unroll
        for (int j = 0; j < 8; j++) s[j] = make_float4(0.f, 0.f, 0.f, 0.f);

        #pragma unroll
        for (int st = 0; st < 4; st++) {
            uint32_t sc = st * 32;
            uint32_t ah[4];
            ldsm_x4(ah, QH + q_off + sc);
            #pragma unroll
            for (int hb = 0; hb < 2; hb++) {
                uint32_t boff = (hb ? r_off1 : r_off0) + sc;
                uint32_t bh0[4], bh1[4], bl0[4], bl1[4];
                ldsm_x4(bh0, KH + boff);
                ldsm_x4(bh1, KH + boff + 16);
                ldsm_x4(bl0, KL + boff);
                ldsm_x4(bl1, KL + boff + 16);
                #pragma unroll
                for (int j = 0; j < 4; j++) mma16(s[hb*4+j], ah, bh0[j], bh1[j]);
                #pragma unroll
                for (int j = 0; j < 4; j++) mma16(s[hb*4+j], ah, bl0[j], bl1[j]);
            }
        }

        float mtA = -1e30f, mtB = -1e30f;
        #pragma unroll
        for (int nf = 0; nf < 8; nf++) {
            mtA = fmaxf(mtA, fmaxf(s[nf].x, s[nf].y));
            mtB = fmaxf(mtB, fmaxf(s[nf].z, s[nf].w));
        }
        mtA = fmaxf(mtA, __shfl_xor_sync(0xffffffffu, mtA, 1));
        mtA = fmaxf(mtA, __shfl_xor_sync(0xffffffffu, mtA, 2));
        mtB = fmaxf(mtB, __shfl_xor_sync(0xffffffffu, mtB, 1));
        mtB = fmaxf(mtB, __shfl_xor_sync(0xffffffffu, mtB, 2));

        float mnA = fmaxf(mA, mtA), mnB = fmaxf(mB, mtB);
        float alA = __expf(mA - mnA), alB = __expf(mB - mnB);
        float sumA = 0.f, sumB = 0.f;
        #pragma unroll
        for (int nf = 0; nf < 8; nf++) {
            s[nf].x = __expf(s[nf].x - mnA);
            s[nf].y = __expf(s[nf].y - mnA);
            s[nf].z = __expf(s[nf].z - mnB);
            s[nf].w = __expf(s[nf].w - mnB);
            sumA += s[nf].x + s[nf].y;
            sumB += s[nf].z + s[nf].w;
        }
        sumA += __shfl_xor_sync(0xffffffffu, sumA, 1);
        sumA += __shfl_xor_sync(0xffffffffu, sumA, 2);
        sumB += __shfl_xor_sync(0xffffffffu, sumB, 1);
        sumB += __shfl_xor_sync(0xffffffffu, sumB, 2);
        lA = lA * alA + sumA; mA = mnA;
        lB = lB * alB + sumB; mB = mnB;
        #pragma unroll
        for (int nf = 0; nf < 8; nf++) {
            o[nf].x *= alA; o[nf].y *= alA;
            o[nf].z *= alB; o[nf].w *= alB;
        }

        #pragma unroll
        for (int st = 0; st < 4; st++) {
            uint32_t pah[4];
            pah[0] = pack2(s[2*st].x,   s[2*st].y);
            pah[1] = pack2(s[2*st].z,   s[2*st].w);
            pah[2] = pack2(s[2*st+1].x, s[2*st+1].y);
            pah[3] = pack2(s[2*st+1].z, s[2*st+1].w);
            uint32_t stoff = (uint32_t)(st * 16 * 36) * 4;
            #pragma unroll
            for (int egp = 0; egp < 2; egp++) {
                uint32_t e0 = (uint32_t)(egp * 2) * 32;
                uint32_t vh0[4], vh1[4], vl0[4], vl1[4];
                ldsm_x4t(vh0, VH + v_off + stoff + e0);
                ldsm_x4t(vh1, VH + v_off + stoff + e0 + 32);
                ldsm_x4t(vl0, VL + v_off + stoff + e0);
                ldsm_x4t(vl1, VL + v_off + stoff + e0 + 32);
                int nb = egp * 4;
                mma16(o[nb+0], pah, vh0[0], vh0[1]);
                mma16(o[nb+1], pah, vh0[2], vh0[3]);
                mma16(o[nb+2], pah, vh1[0], vh1[1]);
                mma16(o[nb+3], pah, vh1[2], vh1[3]);
                mma16(o[nb+0], pah, vl0[0], vl0[1]);
                mma16(o[nb+1], pah, vl0[2], vl0[3]);
                mma16(o[nb+2], pah, vl1[0], vl1[1]);
                mma16(o[nb+3], pah, vl1[2], vl1[3]);
            }
        }
        __syncthreads();
    }

    float invA = 1.f / lA, invB = 1.f / lB;
    int qA = q0 + wq0 + g, qB = qA + 8;
    #pragma unroll
    for (int nf = 0; nf < 8; nf++) {
        int pr = h * 32 + nf * 4 + qd;
        g_Hh[((size_t)b * SEQ + qA) * KPAIRS + pr] =
            pack2(o[nf].x * invA, o[nf].y * invA);
        g_Hh[((size_t)b * SEQ + qB) * KPAIRS + pr] =
            pack2(o[nf].z * invB, o[nf].w * invB);
    }
}

// ---------------------------------------------------------------------------
extern "C" void kernel_launch(void* const* d_in, const int* in_sizes, int n_in,
                              void* d_out, int out_size)
{
    const float* q  = (const float*)d_in[0];
    const float* k  = (const float*)d_in[1];
    const float* v  = (const float*)d_in[2];
    const float* Wq = (const float*)d_in[3];
    const float* Wk = (const float*)d_in[4];
    const float* Wv = (const float*)d_in[5];
    const float* Wo = (const float*)d_in[6];
    float* out = (float*)d_out;

    cudaFuncSetAttribute(gemm_qkv, cudaFuncAttributeMaxDynamicSharedMemorySize, GEMM_SMEM);
    cudaFuncSetAttribute(gemm_out, cudaFuncAttributeMaxDynamicSharedMemorySize, GEMM_SMEM);
    cudaFuncSetAttribute(attn_p,   cudaFuncAttributeMaxDynamicSharedMemorySize, ATTN_SMEM);

    presplit_all<<<dim3(NP / 1024, 1, 7), 256>>>(q, k, v, Wq, Wk, Wv, Wo);

    gemm_qkv<<<dim3(DMODEL / 128, MROWS / 128, 3), 256, GEMM_SMEM>>>();

    attn_p<<<dim3(SEQ / 128, NHEADS, BATCH), 256, ATTN_SMEM>>>();

    gemm_out<<<dim3(DMODEL / 128, MROWS / 128), 256, GEMM_SMEM>>>(out);
}

// round 16
// speedup vs baseline: 1.1207x; 1.0171x over previous
#include <cuda_runtime.h>
#include <cuda_fp16.h>
#include <stdint.h>

#define NHEADS 16
#define BATCH  2
#define SEQ    2048
#define DMODEL 1024
#define HID    64
#define MROWS  4096
#define KPAIRS 512          // DMODEL/2
#define NORM   0.125f
#define NP     (MROWS*KPAIRS)
#define WN     (DMODEL*KPAIRS)

// ---------------------------------------------------------------------------
// Global scratch. Inputs + Q + H are hi-only; K,V and weights are split.
// ---------------------------------------------------------------------------
__device__ uint32_t g_Xh[3u*NP];                  // inputs hi [which][m][kpair]
__device__ uint32_t g_Wh[4u*WN], g_Wl[4u*WN];     // weights hi/lo [which][n][kpair]
__device__ uint32_t g_Qh[NP];                     // [h][b][s][32 epairs] (hi only)
__device__ uint32_t g_Kh[NP], g_Kl[NP];
__device__ uint32_t g_Vh[NP], g_Vl[NP];
__device__ uint32_t g_Hh[NP];                     // attn out hi [b][s][512 pairs]

// ---------------------------------------------------------------------------
// helpers
// ---------------------------------------------------------------------------
__device__ __forceinline__ void split2(float x, float y, uint32_t& hi, uint32_t& lo) {
    __half hx = __float2half_rn(x), hy = __float2half_rn(y);
    __half2 H = __halves2half2(hx, hy);
    __half2 L = __floats2half2_rn(x - __half2float(hx), y - __half2float(hy));
    hi = *reinterpret_cast<uint32_t*>(&H);
    lo = *reinterpret_cast<uint32_t*>(&L);
}
__device__ __forceinline__ uint32_t pack2(float x, float y) {
    __half2 H = __floats2half2_rn(x, y);
    return *reinterpret_cast<uint32_t*>(&H);
}
__device__ __forceinline__ uint32_t smem_u32(const void* p) {
    return (uint32_t)__cvta_generic_to_shared(p);
}
__device__ __forceinline__ void ldsm_x4(uint32_t* r, uint32_t addr) {
    asm volatile("ldmatrix.sync.aligned.m8n8.x4.shared.b16 {%0,%1,%2,%3},[%4];"
        : "=r"(r[0]), "=r"(r[1]), "=r"(r[2]), "=r"(r[3]) : "r"(addr));
}
__device__ __forceinline__ void ldsm_x4t(uint32_t* r, uint32_t addr) {
    asm volatile("ldmatrix.sync.aligned.m8n8.x4.trans.shared.b16 {%0,%1,%2,%3},[%4];"
        : "=r"(r[0]), "=r"(r[1]), "=r"(r[2]), "=r"(r[3]) : "r"(addr));
}
// fp32-accumulate fp16 MMA
__device__ __forceinline__ void mma16(float4& d, const uint32_t* a,
                                      uint32_t b0, uint32_t b1) {
    asm volatile(
        "mma.sync.aligned.m16n8k16.row.col.f32.f16.f16.f32 "
        "{%0,%1,%2,%3},{%4,%5,%6,%7},{%8,%9},{%0,%1,%2,%3};"
        : "+f"(d.x), "+f"(d.y), "+f"(d.z), "+f"(d.w)
        : "r"(a[0]), "r"(a[1]), "r"(a[2]), "r"(a[3]), "r"(b0), "r"(b1));
}
// fp16-accumulate fp16 MMA — lo correction terms only
__device__ __forceinline__ void mma16h(uint2& d, const uint32_t* a,
                                       uint32_t b0, uint32_t b1) {
    asm volatile(
        "mma.sync.aligned.m16n8k16.row.col.f16.f16.f16.f16 "
        "{%0,%1},{%2,%3,%4,%5},{%6,%7},{%0,%1};"
        : "+r"(d.x), "+r"(d.y)
        : "r"(a[0]), "r"(a[1]), "r"(a[2]), "r"(a[3]), "r"(b0), "r"(b1));
}
__device__ __forceinline__ void cp16(uint32_t dst, const void* src) {
    asm volatile("cp.async.cg.shared.global [%0], [%1], 16;" :: "r"(dst), "l"(src));
}
#define CP_COMMIT() asm volatile("cp.async.commit_group;")
#define CP_WAIT(N)  asm volatile("cp.async.wait_group %0;" :: "n"(N))

// ---------------------------------------------------------------------------
// Presplit — single merged launch. z=0..2: inputs q/k/v (4 pairs/thread,
// vectorized, hi-only). z=3..6: weights Wq/Wk/Wv (scaled) and Wo, 2
// pairs/thread, hi/lo split. Per-element arithmetic identical to R15.
// ---------------------------------------------------------------------------
__global__ void presplit_all(const float* __restrict__ q,
                             const float* __restrict__ k,
                             const float* __restrict__ v,
                             const float* __restrict__ W0,
                             const float* __restrict__ W1,
                             const float* __restrict__ W2,
                             const float* __restrict__ W3) {
    int z = blockIdx.z;
    if (z < 3) {
        const float* src = (z == 0) ? q : (z == 1) ? k : v;
        int i4 = blockIdx.x * 256 + threadIdx.x;     // groups of 4 pairs
        float4 a = ((const float4*)src)[i4 * 2];
        float4 b = ((const float4*)src)[i4 * 2 + 1];
        uint4 o;
        o.x = pack2(a.x, a.y); o.y = pack2(a.z, a.w);
        o.z = pack2(b.x, b.y); o.w = pack2(b.z, b.w);
        ((uint4*)(g_Xh + (size_t)z * NP))[i4] = o;
    } else {
        if (blockIdx.x >= WN / 512) return;          // weights need half the blocks
        int w = z - 3;
        int i2 = blockIdx.x * 256 + threadIdx.x;     // groups of 2 pairs
        int i = i2 * 2;
        int n = i >> 9, p = i & 511;
        uint32_t hh0, ll0, hh1, ll1;
        if (w < 3) {
            const float* W = (w == 0) ? W0 : (w == 1) ? W1 : W2;
            float scale = (w == 0) ? NORM : 1.0f;
            int h = n >> 6, e = n & 63;
            const float* s = W + (size_t)h * DMODEL * HID + (size_t)(2 * p) * HID + e;
            split2(s[0] * scale,       s[HID] * scale,     hh0, ll0);
            split2(s[2 * HID] * scale, s[3 * HID] * scale, hh1, ll1);
        } else {
            split2(W3[(size_t)(2 * p) * DMODEL + n],
                   W3[(size_t)(2 * p + 1) * DMODEL + n], hh0, ll0);
            split2(W3[(size_t)(2 * p + 2) * DMODEL + n],
                   W3[(size_t)(2 * p + 3) * DMODEL + n], hh1, ll1);
        }
        uint32_t* dh = g_Wh + (size_t)w * WN + i;
        uint32_t* dl = g_Wl + (size_t)w * WN + i;
        *(uint2*)dh = make_uint2(hh0, hh1);
        *(uint2*)dl = make_uint2(ll0, ll1);
    }
}

// ---------------------------------------------------------------------------
// QKV projection GEMM (merged z=0,1,2): hi term Ah·Bh fp32 acc; lo term
// Ah·Bl fp16 acc, merged after K loop. BM=BN=128, BK=64, 8 warps (4m x 2n),
// cp.async double-buffered.
// ---------------------------------------------------------------------------
#define GEMM_SMEM (2 * 3 * 4608 * 4)   // 110592 B

__global__ __launch_bounds__(256, 2)
void gemm_qkv()
{
    extern __shared__ uint32_t sg[];   // [2][3][4608]

    const int z    = blockIdx.z;
    const int tid  = threadIdx.x;
    const int lane = tid & 31;
    const int wid  = tid >> 5;
    const int g    = lane >> 2;
    const int qd   = lane & 3;
    const int wm   = wid >> 1;
    const int wn   = wid & 1;
    const int m0   = blockIdx.y * 128;
    const int n0   = blockIdx.x * 128;

    const uint32_t* Ahg = g_Xh + (size_t)z * NP;
    const uint32_t* Bhg = g_Wh + (size_t)z * WN;
    const uint32_t* Blg = g_Wl + (size_t)z * WN;

    const uint32_t SB = smem_u32(sg);
    const int arow = lane & 15, acol = (lane >> 4) * 4;
    const uint32_t a_off0 = ((wm * 32 + arow) * 36 + acol) * 4;
    const uint32_t a_off1 = a_off0 + 16 * 36 * 4;
    const uint32_t b_off0 = ((wn * 64 + lane) * 36) * 4;
    const uint32_t b_off1 = b_off0 + 32 * 36 * 4;

    float4 acc[2][8];
    uint2  accl[2][8];
    #pragma unroll
    for (int i = 0; i < 2; i++)
        #pragma unroll
        for (int j = 0; j < 8; j++) {
            acc[i][j]  = make_float4(0.f, 0.f, 0.f, 0.f);
            accl[i][j] = make_uint2(0u, 0u);
        }

    auto load_tile = [&](int kt, int bf) {
        const uint32_t base = SB + (uint32_t)bf * 13824 * 4;
        int kp0 = kt * 32;
        #pragma unroll
        for (int t = 0; t < 12; t++) {
            int f = tid + t * 256;            // 0..3071
            int arr = f >> 10, gg = f & 1023;
            int row = gg >> 3, ch = gg & 7;
            uint32_t dst = base + (uint32_t)(arr * 4608 + row * 36 + ch * 4) * 4;
            const uint32_t* src =
                (arr == 0) ? Ahg + (size_t)(m0 + row) * KPAIRS + kp0 + ch * 4 :
                (arr == 1) ? Bhg + (size_t)(n0 + row) * KPAIRS + kp0 + ch * 4 :
                             Blg + (size_t)(n0 + row) * KPAIRS + kp0 + ch * 4;
            cp16(dst, src);
        }
    };

    load_tile(0, 0);
    CP_COMMIT();

    for (int kt = 0; kt < 16; kt++) {
        if (kt < 15) { load_tile(kt + 1, (kt + 1) & 1); CP_COMMIT(); CP_WAIT(1); }
        else         { CP_WAIT(0); }
        __syncthreads();

        const uint32_t base = SB + (uint32_t)(kt & 1) * 13824 * 4;
        const uint32_t AHB = base;
        const uint32_t BHB = base + 4608 * 4, BLB = base + 9216 * 4;

        #pragma unroll
        for (int s = 0; s < 4; s++) {
            uint32_t sc = s * 32;
            uint32_t ah0[4], ah1[4];
            ldsm_x4(ah0, AHB + a_off0 + sc);
            ldsm_x4(ah1, AHB + a_off1 + sc);
            #pragma unroll
            for (int hb = 0; hb < 2; hb++) {
                uint32_t boff = (hb ? b_off1 : b_off0) + sc;
                uint32_t bh0[4], bh1[4], bl0[4], bl1[4];
                ldsm_x4(bh0, BHB + boff);
                ldsm_x4(bh1, BHB + boff + 16);
                ldsm_x4(bl0, BLB + boff);
                ldsm_x4(bl1, BLB + boff + 16);
                #pragma unroll
                for (int j = 0; j < 4; j++) mma16(acc[0][hb*4+j], ah0, bh0[j], bh1[j]);
                #pragma unroll
                for (int j = 0; j < 4; j++) mma16(acc[1][hb*4+j], ah1, bh0[j], bh1[j]);
                #pragma unroll
                for (int j = 0; j < 4; j++) mma16h(accl[0][hb*4+j], ah0, bl0[j], bl1[j]);
                #pragma unroll
                for (int j = 0; j < 4; j++) mma16h(accl[1][hb*4+j], ah1, bl0[j], bl1[j]);
            }
        }
        if (kt < 15) __syncthreads();   // last-iter barrier is dead (no reuse)
    }

    // Merge lo (fp16) into hi (fp32); epilogue: Q hi-only; K,V split
    #pragma unroll
    for (int mf = 0; mf < 2; mf++) {
        int mA = m0 + wm * 32 + mf * 16 + g;
        int mB = mA + 8;
        #pragma unroll
        for (int nf = 0; nf < 8; nf++) {
            float2 l0 = __half22float2(*reinterpret_cast<__half2*>(&accl[mf][nf].x));
            float2 l1 = __half22float2(*reinterpret_cast<__half2*>(&accl[mf][nf].y));
            float4 c = acc[mf][nf];
            c.x += l0.x; c.y += l0.y; c.z += l1.x; c.w += l1.y;
            int head = (n0 >> 6) + wn;
            int pr   = nf * 4 + qd;
            int bA = mA >> 11, sA = mA & 2047;
            int bB = mB >> 11, sB = mB & 2047;
            size_t dA = (((size_t)head * BATCH + bA) * SEQ + sA) * 32 + pr;
            size_t dB = (((size_t)head * BATCH + bB) * SEQ + sB) * 32 + pr;
            if (z == 0) {
                g_Qh[dA] = pack2(c.x, c.y);
                g_Qh[dB] = pack2(c.z, c.w);
            } else {
                uint32_t* Oh = (z == 1) ? g_Kh : g_Vh;
                uint32_t* Ol = (z == 1) ? g_Kl : g_Vl;
                uint32_t hh, ll;
                split2(c.x, c.y, hh, ll);
                Oh[dA] = hh; Ol[dA] = ll;
                split2(c.z, c.w, hh, ll);
                Oh[dB] = hh; Ol[dB] = ll;
            }
        }
    }
}

// ---------------------------------------------------------------------------
// Output projection GEMM: hi term fp32 acc, lo term fp16 acc. BK=64.
// ---------------------------------------------------------------------------
__global__ __launch_bounds__(256, 2)
void gemm_out(float* __restrict__ Outf)
{
    extern __shared__ uint32_t sg[];   // [2][3][4608]

    const int tid  = threadIdx.x;
    const int lane = tid & 31;
    const int wid  = tid >> 5;
    const int g    = lane >> 2;
    const int qd   = lane & 3;
    const int wm   = wid >> 1;
    const int wn   = wid & 1;
    const int m0   = blockIdx.y * 128;
    const int n0   = blockIdx.x * 128;

    const uint32_t* Ahg = g_Hh;
    const uint32_t* Bhg = g_Wh + 3u * WN;
    const uint32_t* Blg = g_Wl + 3u * WN;

    const uint32_t SB = smem_u32(sg);
    const int arow = lane & 15, acol = (lane >> 4) * 4;
    const uint32_t a_off0 = ((wm * 32 + arow) * 36 + acol) * 4;
    const uint32_t a_off1 = a_off0 + 16 * 36 * 4;
    const uint32_t b_off0 = ((wn * 64 + lane) * 36) * 4;
    const uint32_t b_off1 = b_off0 + 32 * 36 * 4;

    float4 acc[2][8];
    uint2  accl[2][8];
    #pragma unroll
    for (int i = 0; i < 2; i++)
        #pragma unroll
        for (int j = 0; j < 8; j++) {
            acc[i][j]  = make_float4(0.f, 0.f, 0.f, 0.f);
            accl[i][j] = make_uint2(0u, 0u);
        }

    auto load_tile = [&](int kt, int bf) {
        const uint32_t base = SB + (uint32_t)bf * 13824 * 4;
        int kp0 = kt * 32;
        #pragma unroll
        for (int t = 0; t < 12; t++) {
            int f = tid + t * 256;
            int arr = f >> 10, gg = f & 1023;
            int row = gg >> 3, ch = gg & 7;
            uint32_t dst = base + (uint32_t)(arr * 4608 + row * 36 + ch * 4) * 4;
            const uint32_t* src =
                (arr == 0) ? Ahg + (size_t)(m0 + row) * KPAIRS + kp0 + ch * 4 :
                (arr == 1) ? Bhg + (size_t)(n0 + row) * KPAIRS + kp0 + ch * 4 :
                             Blg + (size_t)(n0 + row) * KPAIRS + kp0 + ch * 4;
            cp16(dst, src);
        }
    };

    load_tile(0, 0);
    CP_COMMIT();

    for (int kt = 0; kt < 16; kt++) {
        if (kt < 15) { load_tile(kt + 1, (kt + 1) & 1); CP_COMMIT(); CP_WAIT(1); }
        else         { CP_WAIT(0); }
        __syncthreads();

        const uint32_t base = SB + (uint32_t)(kt & 1) * 13824 * 4;
        const uint32_t AHB = base;
        const uint32_t BHB = base + 4608 * 4, BLB = base + 9216 * 4;

        #pragma unroll
        for (int s = 0; s < 4; s++) {
            uint32_t sc = s * 32;
            uint32_t ah0[4], ah1[4];
            ldsm_x4(ah0, AHB + a_off0 + sc);
            ldsm_x4(ah1, AHB + a_off1 + sc);
            #pragma unroll
            for (int hb = 0; hb < 2; hb++) {
                uint32_t boff = (hb ? b_off1 : b_off0) + sc;
                uint32_t bh0[4], bh1[4], bl0[4], bl1[4];
                ldsm_x4(bh0, BHB + boff);
                ldsm_x4(bh1, BHB + boff + 16);
                ldsm_x4(bl0, BLB + boff);
                ldsm_x4(bl1, BLB + boff + 16);
                #pragma unroll
                for (int j = 0; j < 4; j++) mma16(acc[0][hb*4+j], ah0, bh0[j], bh1[j]);
                #pragma unroll
                for (int j = 0; j < 4; j++) mma16(acc[1][hb*4+j], ah1, bh0[j], bh1[j]);
                #pragma unroll
                for (int j = 0; j < 4; j++) mma16h(accl[0][hb*4+j], ah0, bl0[j], bl1[j]);
                #pragma unroll
                for (int j = 0; j < 4; j++) mma16h(accl[1][hb*4+j], ah1, bl0[j], bl1[j]);
            }
        }
        if (kt < 15) __syncthreads();   // last-iter barrier is dead
    }

    #pragma unroll
    for (int mf = 0; mf < 2; mf++) {
        int mA = m0 + wm * 32 + mf * 16 + g;
        int mB = mA + 8;
        #pragma unroll
        for (int nf = 0; nf < 8; nf++) {
            float2 l0 = __half22float2(*reinterpret_cast<__half2*>(&accl[mf][nf].x));
            float2 l1 = __half22float2(*reinterpret_cast<__half2*>(&accl[mf][nf].y));
            float4 c = acc[mf][nf];
            c.x += l0.x; c.y += l0.y; c.z += l1.x; c.w += l1.y;
            int n = n0 + wn * 64 + nf * 8 + 2 * qd;
            *(float2*)(Outf + (size_t)mA * DMODEL + n) = make_float2(c.x, c.y);
            *(float2*)(Outf + (size_t)mB * DMODEL + n) = make_float2(c.z, c.w);
        }
    }
}

// ---------------------------------------------------------------------------
// Flash attention — numerics identical to R15 (bitwise).
// S = Qh·(Kh+Kl) 2-term; PV 2-term (Ph·Vh + Ph·Vl).
// ---------------------------------------------------------------------------
#define ATTN_SMEM ((4608 + 2 * 9216) * 4)   // 92160 B

__global__ __launch_bounds__(256, 2)
void attn_p()
{
    extern __shared__ uint32_t sa[];

    const int tid  = threadIdx.x;
    const int lane = tid & 31;
    const int g    = lane >> 2;
    const int qd   = lane & 3;
    const int wq0  = (tid >> 5) * 16;

    const int q0 = blockIdx.x * 128;
    const int h  = blockIdx.y;
    const int b  = blockIdx.z;
    const size_t base32 = ((size_t)h * BATCH + b) * SEQ * 32;

    const uint32_t SB = smem_u32(sa);
    const uint32_t QH = SB;

    const int arow = lane & 15, acol = (lane >> 4) * 4;
    const uint32_t q_off  = ((wq0 + arow) * 36 + acol) * 4;
    const uint32_t r_off0 = (lane * 36) * 4;
    const uint32_t r_off1 = r_off0 + 32 * 36 * 4;
    const uint32_t v_off = (((lane & 7) + ((lane >> 3) & 1) * 8) * 36
                            + (lane >> 4) * 4) * 4;

    auto load_q = [&]() {
        #pragma unroll
        for (int t = 0; t < 4; t++) {
            int f = tid + t * 256;
            int row = f >> 3, ch = f & 7;
            uint32_t dst = SB + (uint32_t)(row * 36 + ch * 4) * 4;
            cp16(dst, g_Qh + base32 + (size_t)(q0 + row) * 32 + ch * 4);
        }
    };
    auto load_kv = [&](int kt, int bf) {
        uint32_t bb = SB + (uint32_t)(4608 + bf * 9216) * 4;
        int k0 = kt * 64;
        #pragma unroll
        for (int t = 0; t < 8; t++) {
            int f = tid + t * 256;
            int arr = f >> 9, gg = f & 511;
            int row = gg >> 3, ch = gg & 7;
            uint32_t dst = bb + (uint32_t)(arr * 2304 + row * 36 + ch * 4) * 4;
            const uint32_t* p =
                (arr == 0) ? g_Kh : (arr == 1) ? g_Kl : (arr == 2) ? g_Vh : g_Vl;
            cp16(dst, p + base32 + (size_t)(k0 + row) * 32 + ch * 4);
        }
    };

    load_q();
    load_kv(0, 0);
    CP_COMMIT();

    float4 o[8];
    #pragma unroll
    for (int j = 0; j < 8; j++) o[j] = make_float4(0.f, 0.f, 0.f, 0.f);
    float mA = -1e30f, mB = -1e30f, lA = 0.f, lB = 0.f;

    for (int kt = 0; kt < SEQ / 64; kt++) {
        if (kt < 31) { load_kv(kt + 1, (kt + 1) & 1); CP_COMMIT(); CP_WAIT(1); }
        else         { CP_WAIT(0); }
        __syncthreads();

        const uint32_t KB = SB + (uint32_t)(4608 + (kt & 1) * 9216) * 4;
        const uint32_t KH = KB, KL = KB + 2304 * 4;
        const uint32_t VH = KB + 4608 * 4, VL = KB + 6912 * 4;

        float4 s[8];
        #pragma unroll
        for (int j = 0; j < 8; j++) s[j] = make_float4(0.f, 0.f, 0.f, 0.f);

        #pragma unroll
        for (int st = 0; st < 4; st++) {
            uint32_t sc = st * 32;
            uint32_t ah[4];
            ldsm_x4(ah, QH + q_off + sc);
            #pragma unroll
            for (int hb = 0; hb < 2; hb++) {
                uint32_t boff = (hb ? r_off1 : r_off0) + sc;
                uint32_t bh0[4], bh1[4], bl0[4], bl1[4];
                ldsm_x4(bh0, KH + boff);
                ldsm_x4(bh1, KH + boff + 16);
                ldsm_x4(bl0, KL + boff);
                ldsm_x4(bl1, KL + boff + 16);
                #pragma unroll
                for (int j = 0; j < 4; j++) mma16(s[hb*4+j], ah, bh0[j], bh1[j]);
                #pragma unroll
                for (int j = 0; j < 4; j++) mma16(s[hb*4+j], ah, bl0[j], bl1[j]);
            }
        }

        float mtA = -1e30f, mtB = -1e30f;
        #pragma unroll
        for (int nf = 0; nf < 8; nf++) {
            mtA = fmaxf(mtA, fmaxf(s[nf].x, s[nf].y));
            mtB = fmaxf(mtB, fmaxf(s[nf].z, s[nf].w));
        }
        mtA = fmaxf(mtA, __shfl_xor_sync(0xffffffffu, mtA, 1));
        mtA = fmaxf(mtA, __shfl_xor_sync(0xffffffffu, mtA, 2));
        mtB = fmaxf(mtB, __shfl_xor_sync(0xffffffffu, mtB, 1));
        mtB = fmaxf(mtB, __shfl_xor_sync(0xffffffffu, mtB, 2));

        float mnA = fmaxf(mA, mtA), mnB = fmaxf(mB, mtB);
        float alA = __expf(mA - mnA), alB = __expf(mB - mnB);
        float sumA = 0.f, sumB = 0.f;
        #pragma unroll
        for (int nf = 0; nf < 8; nf++) {
            s[nf].x = __expf(s[nf].x - mnA);
            s[nf].y = __expf(s[nf].y - mnA);
            s[nf].z = __expf(s[nf].z - mnB);
            s[nf].w = __expf(s[nf].w - mnB);
            sumA += s[nf].x + s[nf].y;
            sumB += s[nf].z + s[nf].w;
        }
        sumA += __shfl_xor_sync(0xffffffffu, sumA, 1);
        sumA += __shfl_xor_sync(0xffffffffu, sumA, 2);
        sumB += __shfl_xor_sync(0xffffffffu, sumB, 1);
        sumB += __shfl_xor_sync(0xffffffffu, sumB, 2);
        lA = lA * alA + sumA; mA = mnA;
        lB = lB * alB + sumB; mB = mnB;
        #pragma unroll
        for (int nf = 0; nf < 8; nf++) {
            o[nf].x *= alA; o[nf].y *= alA;
            o[nf].z *= alB; o[nf].w *= alB;
        }

        #pragma unroll
        for (int st = 0; st < 4; st++) {
            uint32_t pah[4];
            pah[0] = pack2(s[2*st].x,   s[2*st].y);
            pah[1] = pack2(s[2*st].z,   s[2*st].w);
            pah[2] = pack2(s[2*st+1].x, s[2*st+1].y);
            pah[3] = pack2(s[2*st+1].z, s[2*st+1].w);
            uint32_t stoff = (uint32_t)(st * 16 * 36) * 4;
            #pragma unroll
            for (int egp = 0; egp < 2; egp++) {
                uint32_t e0 = (uint32_t)(egp * 2) * 32;
                uint32_t vh0[4], vh1[4], vl0[4], vl1[4];
                ldsm_x4t(vh0, VH + v_off + stoff + e0);
                ldsm_x4t(vh1, VH + v_off + stoff + e0 + 32);
                ldsm_x4t(vl0, VL + v_off + stoff + e0);
                ldsm_x4t(vl1, VL + v_off + stoff + e0 + 32);
                int nb = egp * 4;
                mma16(o[nb+0], pah, vh0[0], vh0[1]);
                mma16(o[nb+1], pah, vh0[2], vh0[3]);
                mma16(o[nb+2], pah, vh1[0], vh1[1]);
                mma16(o[nb+3], pah, vh1[2], vh1[3]);
                mma16(o[nb+0], pah, vl0[0], vl0[1]);
                mma16(o[nb+1], pah, vl0[2], vl0[3]);
                mma16(o[nb+2], pah, vl1[0], vl1[1]);
                mma16(o[nb+3], pah, vl1[2], vl1[3]);
            }
        }
        if (kt < 31) __syncthreads();   // last-iter barrier is dead
    }

    float invA = 1.f / lA, invB = 1.f / lB;
    int qA = q0 + wq0 + g, qB = qA + 8;
    #pragma unroll
    for (int nf = 0; nf < 8; nf++) {
        int pr = h * 32 + nf * 4 + qd;
        g_Hh[((size_t)b * SEQ + qA) * KPAIRS + pr] =
            pack2(o[nf].x * invA, o[nf].y * invA);
        g_Hh[((size_t)b * SEQ + qB) * KPAIRS + pr] =
            pack2(o[nf].z * invB, o[nf].w * invB);
    }
}

// ---------------------------------------------------------------------------
extern "C" void kernel_launch(void* const* d_in, const int* in_sizes, int n_in,
                              void* d_out, int out_size)
{
    const float* q  = (const float*)d_in[0];
    const float* k  = (const float*)d_in[1];
    const float* v  = (const float*)d_in[2];
    const float* Wq = (const float*)d_in[3];
    const float* Wk = (const float*)d_in[4];
    const float* Wv = (const float*)d_in[5];
    const float* Wo = (const float*)d_in[6];
    float* out = (float*)d_out;

    cudaFuncSetAttribute(gemm_qkv, cudaFuncAttributeMaxDynamicSharedMemorySize, GEMM_SMEM);
    cudaFuncSetAttribute(gemm_out, cudaFuncAttributeMaxDynamicSharedMemorySize, GEMM_SMEM);
    cudaFuncSetAttribute(attn_p,   cudaFuncAttributeMaxDynamicSharedMemorySize, ATTN_SMEM);

    presplit_all<<<dim3(NP / 1024, 1, 7), 256>>>(q, k, v, Wq, Wk, Wv, Wo);

    gemm_qkv<<<dim3(DMODEL / 128, MROWS / 128, 3), 256, GEMM_SMEM>>>();

    attn_p<<<dim3(SEQ / 128, NHEADS, BATCH), 256, ATTN_SMEM>>>();

    gemm_out<<<dim3(DMODEL / 128, MROWS / 128), 256, GEMM_SMEM>>>(out);
}

// round 17
// speedup vs baseline: 1.1965x; 1.0676x over previous
#include <cuda_runtime.h>
#include <cuda_fp16.h>
#include <stdint.h>

#define NHEADS 16
#define BATCH  2
#define SEQ    2048
#define DMODEL 1024
#define HID    64
#define MROWS  4096
#define KPAIRS 512          // DMODEL/2
#define NORM   0.125f
#define NP     (MROWS*KPAIRS)
#define WN     (DMODEL*KPAIRS)

// ---------------------------------------------------------------------------
// Global scratch. Inputs + Q + H are hi-only; K,V and weights are split.
// ---------------------------------------------------------------------------
__device__ uint32_t g_Xh[3u*NP];                  // inputs hi [which][m][kpair]
__device__ uint32_t g_Wh[4u*WN], g_Wl[4u*WN];     // weights hi/lo [which][n][kpair]
__device__ uint32_t g_Qh[NP];                     // [h][b][s][32 epairs] (hi only)
__device__ uint32_t g_Kh[NP], g_Kl[NP];
__device__ uint32_t g_Vh[NP], g_Vl[NP];
__device__ uint32_t g_Hh[NP];                     // attn out hi [b][s][512 pairs]

// ---------------------------------------------------------------------------
// helpers
// ---------------------------------------------------------------------------
__device__ __forceinline__ void split2(float x, float y, uint32_t& hi, uint32_t& lo) {
    __half hx = __float2half_rn(x), hy = __float2half_rn(y);
    __half2 H = __halves2half2(hx, hy);
    __half2 L = __floats2half2_rn(x - __half2float(hx), y - __half2float(hy));
    hi = *reinterpret_cast<uint32_t*>(&H);
    lo = *reinterpret_cast<uint32_t*>(&L);
}
__device__ __forceinline__ uint32_t pack2(float x, float y) {
    __half2 H = __floats2half2_rn(x, y);
    return *reinterpret_cast<uint32_t*>(&H);
}
__device__ __forceinline__ uint32_t smem_u32(const void* p) {
    return (uint32_t)__cvta_generic_to_shared(p);
}
__device__ __forceinline__ void ldsm_x4(uint32_t* r, uint32_t addr) {
    asm volatile("ldmatrix.sync.aligned.m8n8.x4.shared.b16 {%0,%1,%2,%3},[%4];"
        : "=r"(r[0]), "=r"(r[1]), "=r"(r[2]), "=r"(r[3]) : "r"(addr));
}
__device__ __forceinline__ void ldsm_x4t(uint32_t* r, uint32_t addr) {
    asm volatile("ldmatrix.sync.aligned.m8n8.x4.trans.shared.b16 {%0,%1,%2,%3},[%4];"
        : "=r"(r[0]), "=r"(r[1]), "=r"(r[2]), "=r"(r[3]) : "r"(addr));
}
// fp32-accumulate fp16 MMA
__device__ __forceinline__ void mma16(float4& d, const uint32_t* a,
                                      uint32_t b0, uint32_t b1) {
    asm volatile(
        "mma.sync.aligned.m16n8k16.row.col.f32.f16.f16.f32 "
        "{%0,%1,%2,%3},{%4,%5,%6,%7},{%8,%9},{%0,%1,%2,%3};"
        : "+f"(d.x), "+f"(d.y), "+f"(d.z), "+f"(d.w)
        : "r"(a[0]), "r"(a[1]), "r"(a[2]), "r"(a[3]), "r"(b0), "r"(b1));
}
// fp16-accumulate fp16 MMA — lo correction terms only
__device__ __forceinline__ void mma16h(uint2& d, const uint32_t* a,
                                       uint32_t b0, uint32_t b1) {
    asm volatile(
        "mma.sync.aligned.m16n8k16.row.col.f16.f16.f16.f16 "
        "{%0,%1},{%2,%3,%4,%5},{%6,%7},{%0,%1};"
        : "+r"(d.x), "+r"(d.y)
        : "r"(a[0]), "r"(a[1]), "r"(a[2]), "r"(a[3]), "r"(b0), "r"(b1));
}
__device__ __forceinline__ void cp16(uint32_t dst, const void* src) {
    asm volatile("cp.async.cg.shared.global [%0], [%1], 16;" :: "r"(dst), "l"(src));
}
#define CP_COMMIT() asm volatile("cp.async.commit_group;")
#define CP_WAIT(N)  asm volatile("cp.async.wait_group %0;" :: "n"(N))

// ---------------------------------------------------------------------------
// Presplit — single merged launch (identical to R16).
// ---------------------------------------------------------------------------
__global__ void presplit_all(const float* __restrict__ q,
                             const float* __restrict__ k,
                             const float* __restrict__ v,
                             const float* __restrict__ W0,
                             const float* __restrict__ W1,
                             const float* __restrict__ W2,
                             const float* __restrict__ W3) {
    int z = blockIdx.z;
    if (z < 3) {
        const float* src = (z == 0) ? q : (z == 1) ? k : v;
        int i4 = blockIdx.x * 256 + threadIdx.x;     // groups of 4 pairs
        float4 a = ((const float4*)src)[i4 * 2];
        float4 b = ((const float4*)src)[i4 * 2 + 1];
        uint4 o;
        o.x = pack2(a.x, a.y); o.y = pack2(a.z, a.w);
        o.z = pack2(b.x, b.y); o.w = pack2(b.z, b.w);
        ((uint4*)(g_Xh + (size_t)z * NP))[i4] = o;
    } else {
        if (blockIdx.x >= WN / 512) return;
        int w = z - 3;
        int i2 = blockIdx.x * 256 + threadIdx.x;
        int i = i2 * 2;
        int n = i >> 9, p = i & 511;
        uint32_t hh0, ll0, hh1, ll1;
        if (w < 3) {
            const float* W = (w == 0) ? W0 : (w == 1) ? W1 : W2;
            float scale = (w == 0) ? NORM : 1.0f;
            int h = n >> 6, e = n & 63;
            const float* s = W + (size_t)h * DMODEL * HID + (size_t)(2 * p) * HID + e;
            split2(s[0] * scale,       s[HID] * scale,     hh0, ll0);
            split2(s[2 * HID] * scale, s[3 * HID] * scale, hh1, ll1);
        } else {
            split2(W3[(size_t)(2 * p) * DMODEL + n],
                   W3[(size_t)(2 * p + 1) * DMODEL + n], hh0, ll0);
            split2(W3[(size_t)(2 * p + 2) * DMODEL + n],
                   W3[(size_t)(2 * p + 3) * DMODEL + n], hh1, ll1);
        }
        uint32_t* dh = g_Wh + (size_t)w * WN + i;
        uint32_t* dl = g_Wl + (size_t)w * WN + i;
        *(uint2*)dh = make_uint2(hh0, hh1);
        *(uint2*)dl = make_uint2(ll0, ll1);
    }
}

// ---------------------------------------------------------------------------
// QKV projection GEMM — identical math to R16; n-tile offset parameter for
// head-group partitioning (bx0=0: heads 0-7, bx0=4: heads 8-15).
// ---------------------------------------------------------------------------
#define GEMM_SMEM (2 * 3 * 4608 * 4)   // 110592 B

__global__ __launch_bounds__(256, 2)
void gemm_qkv(int bx0)
{
    extern __shared__ uint32_t sg[];   // [2][3][4608]

    const int z    = blockIdx.z;
    const int tid  = threadIdx.x;
    const int lane = tid & 31;
    const int wid  = tid >> 5;
    const int g    = lane >> 2;
    const int qd   = lane & 3;
    const int wm   = wid >> 1;
    const int wn   = wid & 1;
    const int m0   = blockIdx.y * 128;
    const int n0   = (blockIdx.x + bx0) * 128;

    const uint32_t* Ahg = g_Xh + (size_t)z * NP;
    const uint32_t* Bhg = g_Wh + (size_t)z * WN;
    const uint32_t* Blg = g_Wl + (size_t)z * WN;

    const uint32_t SB = smem_u32(sg);
    const int arow = lane & 15, acol = (lane >> 4) * 4;
    const uint32_t a_off0 = ((wm * 32 + arow) * 36 + acol) * 4;
    const uint32_t a_off1 = a_off0 + 16 * 36 * 4;
    const uint32_t b_off0 = ((wn * 64 + lane) * 36) * 4;
    const uint32_t b_off1 = b_off0 + 32 * 36 * 4;

    float4 acc[2][8];
    uint2  accl[2][8];
    #pragma unroll
    for (int i = 0; i < 2; i++)
        #pragma unroll
        for (int j = 0; j < 8; j++) {
            acc[i][j]  = make_float4(0.f, 0.f, 0.f, 0.f);
            accl[i][j] = make_uint2(0u, 0u);
        }

    auto load_tile = [&](int kt, int bf) {
        const uint32_t base = SB + (uint32_t)bf * 13824 * 4;
        int kp0 = kt * 32;
        #pragma unroll
        for (int t = 0; t < 12; t++) {
            int f = tid + t * 256;            // 0..3071
            int arr = f >> 10, gg = f & 1023;
            int row = gg >> 3, ch = gg & 7;
            uint32_t dst = base + (uint32_t)(arr * 4608 + row * 36 + ch * 4) * 4;
            const uint32_t* src =
                (arr == 0) ? Ahg + (size_t)(m0 + row) * KPAIRS + kp0 + ch * 4 :
                (arr == 1) ? Bhg + (size_t)(n0 + row) * KPAIRS + kp0 + ch * 4 :
                             Blg + (size_t)(n0 + row) * KPAIRS + kp0 + ch * 4;
            cp16(dst, src);
        }
    };

    load_tile(0, 0);
    CP_COMMIT();

    for (int kt = 0; kt < 16; kt++) {
        if (kt < 15) { load_tile(kt + 1, (kt + 1) & 1); CP_COMMIT(); CP_WAIT(1); }
        else         { CP_WAIT(0); }
        __syncthreads();

        const uint32_t base = SB + (uint32_t)(kt & 1) * 13824 * 4;
        const uint32_t AHB = base;
        const uint32_t BHB = base + 4608 * 4, BLB = base + 9216 * 4;

        #pragma unroll
        for (int s = 0; s < 4; s++) {
            uint32_t sc = s * 32;
            uint32_t ah0[4], ah1[4];
            ldsm_x4(ah0, AHB + a_off0 + sc);
            ldsm_x4(ah1, AHB + a_off1 + sc);
            #pragma unroll
            for (int hb = 0; hb < 2; hb++) {
                uint32_t boff = (hb ? b_off1 : b_off0) + sc;
                uint32_t bh0[4], bh1[4], bl0[4], bl1[4];
                ldsm_x4(bh0, BHB + boff);
                ldsm_x4(bh1, BHB + boff + 16);
                ldsm_x4(bl0, BLB + boff);
                ldsm_x4(bl1, BLB + boff + 16);
                #pragma unroll
                for (int j = 0; j < 4; j++) mma16(acc[0][hb*4+j], ah0, bh0[j], bh1[j]);
                #pragma unroll
                for (int j = 0; j < 4; j++) mma16(acc[1][hb*4+j], ah1, bh0[j], bh1[j]);
                #pragma unroll
                for (int j = 0; j < 4; j++) mma16h(accl[0][hb*4+j], ah0, bl0[j], bl1[j]);
                #pragma unroll
                for (int j = 0; j < 4; j++) mma16h(accl[1][hb*4+j], ah1, bl0[j], bl1[j]);
            }
        }
        if (kt < 15) __syncthreads();   // last-iter barrier is dead
    }

    // Merge lo (fp16) into hi (fp32); epilogue: Q hi-only; K,V split
    #pragma unroll
    for (int mf = 0; mf < 2; mf++) {
        int mA = m0 + wm * 32 + mf * 16 + g;
        int mB = mA + 8;
        #pragma unroll
        for (int nf = 0; nf < 8; nf++) {
            float2 l0 = __half22float2(*reinterpret_cast<__half2*>(&accl[mf][nf].x));
            float2 l1 = __half22float2(*reinterpret_cast<__half2*>(&accl[mf][nf].y));
            float4 c = acc[mf][nf];
            c.x += l0.x; c.y += l0.y; c.z += l1.x; c.w += l1.y;
            int head = (n0 >> 6) + wn;
            int pr   = nf * 4 + qd;
            int bA = mA >> 11, sA = mA & 2047;
            int bB = mB >> 11, sB = mB & 2047;
            size_t dA = (((size_t)head * BATCH + bA) * SEQ + sA) * 32 + pr;
            size_t dB = (((size_t)head * BATCH + bB) * SEQ + sB) * 32 + pr;
            if (z == 0) {
                g_Qh[dA] = pack2(c.x, c.y);
                g_Qh[dB] = pack2(c.z, c.w);
            } else {
                uint32_t* Oh = (z == 1) ? g_Kh : g_Vh;
                uint32_t* Ol = (z == 1) ? g_Kl : g_Vl;
                uint32_t hh, ll;
                split2(c.x, c.y, hh, ll);
                Oh[dA] = hh; Ol[dA] = ll;
                split2(c.z, c.w, hh, ll);
                Oh[dB] = hh; Ol[dB] = ll;
            }
        }
    }
}

// ---------------------------------------------------------------------------
// Output projection GEMM — identical to R16.
// ---------------------------------------------------------------------------
__global__ __launch_bounds__(256, 2)
void gemm_out(float* __restrict__ Outf)
{
    extern __shared__ uint32_t sg[];   // [2][3][4608]

    const int tid  = threadIdx.x;
    const int lane = tid & 31;
    const int wid  = tid >> 5;
    const int g    = lane >> 2;
    const int qd   = lane & 3;
    const int wm   = wid >> 1;
    const int wn   = wid & 1;
    const int m0   = blockIdx.y * 128;
    const int n0   = blockIdx.x * 128;

    const uint32_t* Ahg = g_Hh;
    const uint32_t* Bhg = g_Wh + 3u * WN;
    const uint32_t* Blg = g_Wl + 3u * WN;

    const uint32_t SB = smem_u32(sg);
    const int arow = lane & 15, acol = (lane >> 4) * 4;
    const uint32_t a_off0 = ((wm * 32 + arow) * 36 + acol) * 4;
    const uint32_t a_off1 = a_off0 + 16 * 36 * 4;
    const uint32_t b_off0 = ((wn * 64 + lane) * 36) * 4;
    const uint32_t b_off1 = b_off0 + 32 * 36 * 4;

    float4 acc[2][8];
    uint2  accl[2][8];
    #pragma unroll
    for (int i = 0; i < 2; i++)
        #pragma unroll
        for (int j = 0; j < 8; j++) {
            acc[i][j]  = make_float4(0.f, 0.f, 0.f, 0.f);
            accl[i][j] = make_uint2(0u, 0u);
        }

    auto load_tile = [&](int kt, int bf) {
        const uint32_t base = SB + (uint32_t)bf * 13824 * 4;
        int kp0 = kt * 32;
        #pragma unroll
        for (int t = 0; t < 12; t++) {
            int f = tid + t * 256;
            int arr = f >> 10, gg = f & 1023;
            int row = gg >> 3, ch = gg & 7;
            uint32_t dst = base + (uint32_t)(arr * 4608 + row * 36 + ch * 4) * 4;
            const uint32_t* src =
                (arr == 0) ? Ahg + (size_t)(m0 + row) * KPAIRS + kp0 + ch * 4 :
                (arr == 1) ? Bhg + (size_t)(n0 + row) * KPAIRS + kp0 + ch * 4 :
                             Blg + (size_t)(n0 + row) * KPAIRS + kp0 + ch * 4;
            cp16(dst, src);
        }
    };

    load_tile(0, 0);
    CP_COMMIT();

    for (int kt = 0; kt < 16; kt++) {
        if (kt < 15) { load_tile(kt + 1, (kt + 1) & 1); CP_COMMIT(); CP_WAIT(1); }
        else         { CP_WAIT(0); }
        __syncthreads();

        const uint32_t base = SB + (uint32_t)(kt & 1) * 13824 * 4;
        const uint32_t AHB = base;
        const uint32_t BHB = base + 4608 * 4, BLB = base + 9216 * 4;

        #pragma unroll
        for (int s = 0; s < 4; s++) {
            uint32_t sc = s * 32;
            uint32_t ah0[4], ah1[4];
            ldsm_x4(ah0, AHB + a_off0 + sc);
            ldsm_x4(ah1, AHB + a_off1 + sc);
            #pragma unroll
            for (int hb = 0; hb < 2; hb++) {
                uint32_t boff = (hb ? b_off1 : b_off0) + sc;
                uint32_t bh0[4], bh1[4], bl0[4], bl1[4];
                ldsm_x4(bh0, BHB + boff);
                ldsm_x4(bh1, BHB + boff + 16);
                ldsm_x4(bl0, BLB + boff);
                ldsm_x4(bl1, BLB + boff + 16);
                #pragma unroll
                for (int j = 0; j < 4; j++) mma16(acc[0][hb*4+j], ah0, bh0[j], bh1[j]);
                #pragma unroll
                for (int j = 0; j < 4; j++) mma16(acc[1][hb*4+j], ah1, bh0[j], bh1[j]);
                #pragma unroll
                for (int j = 0; j < 4; j++) mma16h(accl[0][hb*4+j], ah0, bl0[j], bl1[j]);
                #pragma unroll
                for (int j = 0; j < 4; j++) mma16h(accl[1][hb*4+j], ah1, bl0[j], bl1[j]);
            }
        }
        if (kt < 15) __syncthreads();   // last-iter barrier is dead
    }

    #pragma unroll
    for (int mf = 0; mf < 2; mf++) {
        int mA = m0 + wm * 32 + mf * 16 + g;
        int mB = mA + 8;
        #pragma unroll
        for (int nf = 0; nf < 8; nf++) {
            float2 l0 = __half22float2(*reinterpret_cast<__half2*>(&accl[mf][nf].x));
            float2 l1 = __half22float2(*reinterpret_cast<__half2*>(&accl[mf][nf].y));
            float4 c = acc[mf][nf];
            c.x += l0.x; c.y += l0.y; c.z += l1.x; c.w += l1.y;
            int n = n0 + wn * 64 + nf * 8 + 2 * qd;
            *(float2*)(Outf + (size_t)mA * DMODEL + n) = make_float2(c.x, c.y);
            *(float2*)(Outf + (size_t)mB * DMODEL + n) = make_float2(c.z, c.w);
        }
    }
}

// ---------------------------------------------------------------------------
// Flash attention — identical math to R16; head offset parameter.
// S = Qh·(Kh+Kl) 2-term; PV 2-term (Ph·Vh + Ph·Vl).
// ---------------------------------------------------------------------------
#define ATTN_SMEM ((4608 + 2 * 9216) * 4)   // 92160 B

__global__ __launch_bounds__(256, 2)
void attn_p(int h0)
{
    extern __shared__ uint32_t sa[];

    const int tid  = threadIdx.x;
    const int lane = tid & 31;
    const int g    = lane >> 2;
    const int qd   = lane & 3;
    const int wq0  = (tid >> 5) * 16;

    const int q0 = blockIdx.x * 128;
    const int h  = blockIdx.y + h0;
    const int b  = blockIdx.z;
    const size_t base32 = ((size_t)h * BATCH + b) * SEQ * 32;

    const uint32_t SB = smem_u32(sa);
    const uint32_t QH = SB;

    const int arow = lane & 15, acol = (lane >> 4) * 4;
    const uint32_t q_off  = ((wq0 + arow) * 36 + acol) * 4;
    const uint32_t r_off0 = (lane * 36) * 4;
    const uint32_t r_off1 = r_off0 + 32 * 36 * 4;
    const uint32_t v_off = (((lane & 7) + ((lane >> 3) & 1) * 8) * 36
                            + (lane >> 4) * 4) * 4;

    auto load_q = [&]() {
        #pragma unroll
        for (int t = 0; t < 4; t++) {
            int f = tid + t * 256;
            int row = f >> 3, ch = f & 7;
            uint32_t dst = SB + (uint32_t)(row * 36 + ch * 4) * 4;
            cp16(dst, g_Qh + base32 + (size_t)(q0 + row) * 32 + ch * 4);
        }
    };
    auto load_kv = [&](int kt, int bf) {
        uint32_t bb = SB + (uint32_t)(4608 + bf * 9216) * 4;
        int k0 = kt * 64;
        #pragma unroll
        for (int t = 0; t < 8; t++) {
            int f = tid + t * 256;
            int arr = f >> 9, gg = f & 511;
            int row = gg >> 3, ch = gg & 7;
            uint32_t dst = bb + (uint32_t)(arr * 2304 + row * 36 + ch * 4) * 4;
            const uint32_t* p =
                (arr == 0) ? g_Kh : (arr == 1) ? g_Kl : (arr == 2) ? g_Vh : g_Vl;
            cp16(dst, p + base32 + (size_t)(k0 + row) * 32 + ch * 4);
        }
    };

    load_q();
    load_kv(0, 0);
    CP_COMMIT();

    float4 o[8];
    #pragma unroll
    for (int j = 0; j < 8; j++) o[j] = make_float4(0.f, 0.f, 0.f, 0.f);
    float mA = -1e30f, mB = -1e30f, lA = 0.f, lB = 0.f;

    for (int kt = 0; kt < SEQ / 64; kt++) {
        if (kt < 31) { load_kv(kt + 1, (kt + 1) & 1); CP_COMMIT(); CP_WAIT(1); }
        else         { CP_WAIT(0); }
        __syncthreads();

        const uint32_t KB = SB + (uint32_t)(4608 + (kt & 1) * 9216) * 4;
        const uint32_t KH = KB, KL = KB + 2304 * 4;
        const uint32_t VH = KB + 4608 * 4, VL = KB + 6912 * 4;

        float4 s[8];
        #pragma unroll
        for (int j = 0; j < 8; j++) s[j] = make_float4(0.f, 0.f, 0.f, 0.f);

        #pragma unroll
        for (int st = 0; st < 4; st++) {
            uint32_t sc = st * 32;
            uint32_t ah[4];
            ldsm_x4(ah, QH + q_off + sc);
            #pragma unroll
            for (int hb = 0; hb < 2; hb++) {
                uint32_t boff = (hb ? r_off1 : r_off0) + sc;
                uint32_t bh0[4], bh1[4], bl0[4], bl1[4];
                ldsm_x4(bh0, KH + boff);
                ldsm_x4(bh1, KH + boff + 16);
                ldsm_x4(bl0, KL + boff);
                ldsm_x4(bl1, KL + boff + 16);
                #pragma unroll
                for (int j = 0; j < 4; j++) mma16(s[hb*4+j], ah, bh0[j], bh1[j]);
                #pragma unroll
                for (int j = 0; j < 4; j++) mma16(s[hb*4+j], ah, bl0[j], bl1[j]);
            }
        }

        float mtA = -1e30f, mtB = -1e30f;
        #pragma unroll
        for (int nf = 0; nf < 8; nf++) {
            mtA = fmaxf(mtA, fmaxf(s[nf].x, s[nf].y));
            mtB = fmaxf(mtB, fmaxf(s[nf].z, s[nf].w));
        }
        mtA = fmaxf(mtA, __shfl_xor_sync(0xffffffffu, mtA, 1));
        mtA = fmaxf(mtA, __shfl_xor_sync(0xffffffffu, mtA, 2));
        mtB = fmaxf(mtB, __shfl_xor_sync(0xffffffffu, mtB, 1));
        mtB = fmaxf(mtB, __shfl_xor_sync(0xffffffffu, mtB, 2));

        float mnA = fmaxf(mA, mtA), mnB = fmaxf(mB, mtB);
        float alA = __expf(mA - mnA), alB = __expf(mB - mnB);
        float sumA = 0.f, sumB = 0.f;
        #pragma unroll
        for (int nf = 0; nf < 8; nf++) {
            s[nf].x = __expf(s[nf].x - mnA);
            s[nf].y = __expf(s[nf].y - mnA);
            s[nf].z = __expf(s[nf].z - mnB);
            s[nf].w = __expf(s[nf].w - mnB);
            sumA += s[nf].x + s[nf].y;
            sumB += s[nf].z + s[nf].w;
        }
        sumA += __shfl_xor_sync(0xffffffffu, sumA, 1);
        sumA += __shfl_xor_sync(0xffffffffu, sumA, 2);
        sumB += __shfl_xor_sync(0xffffffffu, sumB, 1);
        sumB += __shfl_xor_sync(0xffffffffu, sumB, 2);
        lA = lA * alA + sumA; mA = mnA;
        lB = lB * alB + sumB; mB = mnB;
        #pragma unroll
        for (int nf = 0; nf < 8; nf++) {
            o[nf].x *= alA; o[nf].y *= alA;
            o[nf].z *= alB; o[nf].w *= alB;
        }

        #pragma unroll
        for (int st = 0; st < 4; st++) {
            uint32_t pah[4];
            pah[0] = pack2(s[2*st].x,   s[2*st].y);
            pah[1] = pack2(s[2*st].z,   s[2*st].w);
            pah[2] = pack2(s[2*st+1].x, s[2*st+1].y);
            pah[3] = pack2(s[2*st+1].z, s[2*st+1].w);
            uint32_t stoff = (uint32_t)(st * 16 * 36) * 4;
            #pragma unroll
            for (int egp = 0; egp < 2; egp++) {
                uint32_t e0 = (uint32_t)(egp * 2) * 32;
                uint32_t vh0[4], vh1[4], vl0[4], vl1[4];
                ldsm_x4t(vh0, VH + v_off + stoff + e0);
                ldsm_x4t(vh1, VH + v_off + stoff + e0 + 32);
                ldsm_x4t(vl0, VL + v_off + stoff + e0);
                ldsm_x4t(vl1, VL + v_off + stoff + e0 + 32);
                int nb = egp * 4;
                mma16(o[nb+0], pah, vh0[0], vh0[1]);
                mma16(o[nb+1], pah, vh0[2], vh0[3]);
                mma16(o[nb+2], pah, vh1[0], vh1[1]);
                mma16(o[nb+3], pah, vh1[2], vh1[3]);
                mma16(o[nb+0], pah, vl0[0], vl0[1]);
                mma16(o[nb+1], pah, vl0[2], vl0[3]);
                mma16(o[nb+2], pah, vl1[0], vl1[1]);
                mma16(o[nb+3], pah, vl1[2], vl1[3]);
            }
        }
        if (kt < 31) __syncthreads();   // last-iter barrier is dead
    }

    float invA = 1.f / lA, invB = 1.f / lB;
    int qA = q0 + wq0 + g, qB = qA + 8;
    #pragma unroll
    for (int nf = 0; nf < 8; nf++) {
        int pr = h * 32 + nf * 4 + qd;
        g_Hh[((size_t)b * SEQ + qA) * KPAIRS + pr] =
            pack2(o[nf].x * invA, o[nf].y * invA);
        g_Hh[((size_t)b * SEQ + qB) * KPAIRS + pr] =
            pack2(o[nf].z * invB, o[nf].w * invB);
    }
}

// ---------------------------------------------------------------------------
// Launch: head-partitioned dual-stream DAG.
//   stream0: presplit -> [fork] qkv(G0) -> attn(G0) -> [join] -> gemm_out
//   s2:               -> qkv(G1) -> attn(G1)
// Streams/events created per call and intentionally NOT destroyed (destroying
// a capture-participating stream invalidates graph capture; kernel_launch is
// only invoked for the correctness run + capture, so the leak is bounded).
// ---------------------------------------------------------------------------
extern "C" void kernel_launch(void* const* d_in, const int* in_sizes, int n_in,
                              void* d_out, int out_size)
{
    const float* q  = (const float*)d_in[0];
    const float* k  = (const float*)d_in[1];
    const float* v  = (const float*)d_in[2];
    const float* Wq = (const float*)d_in[3];
    const float* Wk = (const float*)d_in[4];
    const float* Wv = (const float*)d_in[5];
    const float* Wo = (const float*)d_in[6];
    float* out = (float*)d_out;

    cudaFuncSetAttribute(gemm_qkv, cudaFuncAttributeMaxDynamicSharedMemorySize, GEMM_SMEM);
    cudaFuncSetAttribute(gemm_out, cudaFuncAttributeMaxDynamicSharedMemorySize, GEMM_SMEM);
    cudaFuncSetAttribute(attn_p,   cudaFuncAttributeMaxDynamicSharedMemorySize, ATTN_SMEM);

    cudaStream_t s2;
    cudaStreamCreateWithFlags(&s2, cudaStreamNonBlocking);
    cudaEvent_t evFork, evJoin;
    cudaEventCreateWithFlags(&evFork, cudaEventDisableTiming);
    cudaEventCreateWithFlags(&evJoin, cudaEventDisableTiming);

    // stream 0 (default/capture stream)
    presplit_all<<<dim3(NP / 1024, 1, 7), 256>>>(q, k, v, Wq, Wk, Wv, Wo);
    cudaEventRecord(evFork, 0);
    cudaStreamWaitEvent(s2, evFork, 0);

    // chain G0 on stream 0: heads 0-7
    gemm_qkv<<<dim3(4, MROWS / 128, 3), 256, GEMM_SMEM>>>(0);
    attn_p<<<dim3(SEQ / 128, NHEADS / 2, BATCH), 256, ATTN_SMEM>>>(0);

    // chain G1 on s2: heads 8-15
    gemm_qkv<<<dim3(4, MROWS / 128, 3), 256, GEMM_SMEM, s2>>>(4);
    attn_p<<<dim3(SEQ / 128, NHEADS / 2, BATCH), 256, ATTN_SMEM, s2>>>(8);

    // join, then output projection on stream 0
    cudaEventRecord(evJoin, s2);
    cudaStreamWaitEvent(0, evJoin, 0);
    gemm_out<<<dim3(DMODEL / 128, MROWS / 128), 256, GEMM_SMEM>>>(out);
}